// round 12
// baseline (speedup 1.0000x reference)
#include <cuda_runtime.h>
#include <cuda_bf16.h>
#include <math.h>
#include <cstdint>

// tcgen05 is only legal on arch-specific targets (sm_103a / sm_100a).
// The harness's nvcc also runs a generic compute_103 PTX pass; guard so that
// pass compiles empty bodies (the sm_103a cubin is what actually runs).
#if !defined(__CUDA_ARCH__) || defined(__CUDA_ARCH_FEAT_SM103_ALL) || \
    defined(__CUDA_ARCH_FEAT_SM100_ALL) || defined(__CUDA_ARCH_FEAT_SM101_ALL)
#define HAS_TCGEN05 1
#else
#define HAS_TCGEN05 0
#endif

// Problem dims
#define Bb   128
#define Tt   128
#define Cc   256
#define Hh   4
#define HS   64
#define Ll   6
#define DFF  1024
#define Vv   10000
#define BT   (Bb*Tt)   // 16384
#define VPAD 10240     // 80*128 (LM head padded to 4-tile groups)
#define QKVN 768

// ================= PTX helpers (sm_103a tcgen05) ===========================
__device__ __forceinline__ uint32_t smem_to_u32(const void* p) {
    uint32_t a;
    asm("{ .reg .u64 t; cvta.to.shared.u64 t, %1; cvt.u32.u64 %0, t; }"
        : "=r"(a) : "l"(p));
    return a;
}

#if HAS_TCGEN05
__device__ __forceinline__ uint32_t elect_one_pred() {
    uint32_t pred;
    asm volatile(
        "{\n\t.reg .pred p;\n\telect.sync _|p, 0xFFFFFFFF;\n\t"
        "selp.b32 %0, 1, 0, p;\n\t}"
        : "=r"(pred));
    return pred;
}
#define TCGEN05_ALLOC(smem_addr, nCols) \
    asm volatile("tcgen05.alloc.cta_group::1.sync.aligned.shared::cta.b32 [%0], %1;" \
        :: "r"((uint32_t)(smem_addr)), "r"((uint32_t)(nCols)) : "memory")
#define TCGEN05_DEALLOC(tmem_addr, nCols) \
    asm volatile("tcgen05.dealloc.cta_group::1.sync.aligned.b32 %0, %1;" \
        :: "r"(tmem_addr), "r"((uint32_t)(nCols)))
#define TCGEN05_RELINQ() \
    asm volatile("tcgen05.relinquish_alloc_permit.cta_group::1.sync.aligned;")
#define TCGEN05_COMMIT(mbar) \
    asm volatile("tcgen05.commit.cta_group::1.mbarrier::arrive::one.shared::cluster.b64 [%0];" \
        :: "r"((uint32_t)(mbar)) : "memory")
#define TCGEN05_FENCE_BEFORE() \
    asm volatile("tcgen05.fence::before_thread_sync;" ::: "memory")
#define TCGEN05_FENCE_AFTER() \
    asm volatile("tcgen05.fence::after_thread_sync;" ::: "memory")
#define TCGEN05_WAIT_LD() \
    asm volatile("tcgen05.wait::ld.sync.aligned;" ::: "memory")
#define FENCE_PROXY_ASYNC_SHARED_CTA() \
    asm volatile("fence.proxy.async.shared::cta;" ::: "memory")
#define MBARRIER_INIT(mbar, count) \
    asm volatile("mbarrier.init.shared.b64 [%0], %1;" \
        :: "r"((uint32_t)(mbar)), "r"((uint32_t)(count)) : "memory")
#define MBARRIER_INVAL(mbar) \
    asm volatile("mbarrier.inval.shared.b64 [%0];" :: "r"((uint32_t)(mbar)) : "memory")
// Non-blocking poll: mbarrier.test_wait in a spin loop, no sleep.
#define MBARRIER_POLL(mbar, parity) do { \
    uint32_t _mbar = (uint32_t)(mbar); \
    uint32_t _par  = (uint32_t)(parity); \
    uint32_t _done = 0; \
    while (!_done) { \
        asm volatile( \
            "{\n\t.reg .pred p;\n\t" \
            "mbarrier.test_wait.parity.acquire.cta.shared::cta.b64 p, [%1], %2;\n\t" \
            "selp.b32 %0, 1, 0, p;\n\t}" \
            : "=r"(_done) : "r"(_mbar), "r"(_par) : "memory"); \
    } \
} while (0)
// Async 16B copy global->shared (LDGSTS). Register-free, deep MLP.
__device__ __forceinline__ void cp_async16(uint32_t dst, const void* src) {
    asm volatile("cp.async.cg.shared.global [%0], [%1], 16;"
        :: "r"(dst), "l"(src) : "memory");
}
#define CP_ASYNC_COMMIT() asm volatile("cp.async.commit_group;" ::: "memory")
#define CP_ASYNC_WAIT0()  asm volatile("cp.async.wait_group 0;" ::: "memory")
#define TCGEN05_LD_32X32B_X32(r, tmem_addr) \
    asm volatile( \
        "tcgen05.ld.sync.aligned.32x32b.x32.b32 " \
        "{%0, %1, %2, %3, %4, %5, %6, %7, " \
        " %8, %9, %10, %11, %12, %13, %14, %15, " \
        " %16, %17, %18, %19, %20, %21, %22, %23, " \
        " %24, %25, %26, %27, %28, %29, %30, %31}, [%32];" \
        : "=r"((r)[0]),  "=r"((r)[1]),  "=r"((r)[2]),  "=r"((r)[3]), \
          "=r"((r)[4]),  "=r"((r)[5]),  "=r"((r)[6]),  "=r"((r)[7]), \
          "=r"((r)[8]),  "=r"((r)[9]),  "=r"((r)[10]), "=r"((r)[11]), \
          "=r"((r)[12]), "=r"((r)[13]), "=r"((r)[14]), "=r"((r)[15]), \
          "=r"((r)[16]), "=r"((r)[17]), "=r"((r)[18]), "=r"((r)[19]), \
          "=r"((r)[20]), "=r"((r)[21]), "=r"((r)[22]), "=r"((r)[23]), \
          "=r"((r)[24]), "=r"((r)[25]), "=r"((r)[26]), "=r"((r)[27]), \
          "=r"((r)[28]), "=r"((r)[29]), "=r"((r)[30]), "=r"((r)[31]) \
        : "r"(tmem_addr))

// cg1 bf16 SS MMA (A in SMEM, B in SMEM), fp32 accumulate
__device__ __forceinline__ void mma_bf16_ss(uint32_t d, uint64_t a, uint64_t b,
                                            uint32_t idesc, bool en) {
    uint32_t e = en ? 1u : 0u;
    asm volatile(
        "{\n\t.reg .pred p;\n\t"
        "setp.ne.u32 p, %5, 0;\n\t"
        "tcgen05.mma.cta_group::1.kind::f16 [%0], %1, %2, %3, {%4, %4, %4, %4}, p;\n\t}"
        :: "r"(d), "l"(a), "l"(b), "r"(idesc), "r"(0u), "r"(e)
        : "memory");
}
#endif  // HAS_TCGEN05

// 64-bit SMEM descriptor: SW128, Blackwell v1, LBO=1, SBO=64 (K-major 128B rows)
static __device__ __forceinline__ uint64_t make_desc_sw128(uint32_t addr) {
    const uint64_t base =
        (uint64_t(2)  << 61) | (uint64_t(1) << 46) |
        (uint64_t(64) << 32) | (uint64_t(1) << 16);
    return base | ((uint64_t)(addr >> 4) & 0x3FFF);
}
#define SW128(bo) ((bo) ^ (((bo) >> 3) & 0x70))

// ================= scratch (device globals) ================================
__device__ __align__(16) float g_x  [BT*Cc];
__device__ __align__(16) float g_qkv[BT*QKVN];
// bf16 hi/lo activations
__device__ __align__(16) __nv_bfloat16 g_hh[BT*Cc],  g_hl[BT*Cc];
__device__ __align__(16) __nv_bfloat16 g_ah[BT*Cc],  g_al[BT*Cc];
__device__ __align__(16) __nv_bfloat16 g_fh[BT*DFF], g_fl[BT*DFF];
// transposed+split weights: [N(pad), K] K-major
__device__ __align__(16) __nv_bfloat16 g_qkvT_h[Ll*QKVN*Cc], g_qkvT_l[Ll*QKVN*Cc];
__device__ __align__(16) __nv_bfloat16 g_pT_h [Ll*Cc*Cc],    g_pT_l [Ll*Cc*Cc];
__device__ __align__(16) __nv_bfloat16 g_w1T_h[Ll*DFF*Cc],   g_w1T_l[Ll*DFF*Cc];
__device__ __align__(16) __nv_bfloat16 g_w2T_h[Ll*Cc*DFF],   g_w2T_l[Ll*Cc*DFF];
__device__ __align__(16) __nv_bfloat16 g_lmT_h[VPAD*Cc],     g_lmT_l[VPAD*Cc];

// ================= small kernels ===========================================
// Fused embedding + LN1(layer 0): one block per row. Writes x AND hh/hl.
__global__ void embed_ln_kernel(const int* __restrict__ idx,
                                const float* __restrict__ tok,
                                const float* __restrict__ pos,
                                const float* __restrict__ g,
                                const float* __restrict__ b,
                                float* __restrict__ x,
                                __nv_bfloat16* __restrict__ oh,
                                __nv_bfloat16* __restrict__ ol) {
    int row = blockIdx.x;
    int tid = threadIdx.x;
    int t   = row & (Tt - 1);
    float v = tok[idx[row] * Cc + tid] + pos[t * Cc + tid];
    x[row * Cc + tid] = v;
    float s = v, s2 = v * v;
    #pragma unroll
    for (int off = 16; off > 0; off >>= 1) {
        s  += __shfl_xor_sync(0xffffffffu, s,  off);
        s2 += __shfl_xor_sync(0xffffffffu, s2, off);
    }
    __shared__ float ss[8], ss2[8];
    __shared__ float mean_s, rstd_s;
    int w = tid >> 5, l = tid & 31;
    if (l == 0) { ss[w] = s; ss2[w] = s2; }
    __syncthreads();
    if (tid == 0) {
        float S = 0.f, S2 = 0.f;
        #pragma unroll
        for (int i = 0; i < 8; i++) { S += ss[i]; S2 += ss2[i]; }
        float m   = S * (1.0f / Cc);
        float var = S2 * (1.0f / Cc) - m * m;
        mean_s = m;
        rstd_s = rsqrtf(var + 1e-5f);
    }
    __syncthreads();
    float y = (v - mean_s) * rstd_s * g[tid] + b[tid];
    __nv_bfloat16 hi = __float2bfloat16(y);
    oh[row * Cc + tid] = hi;
    ol[row * Cc + tid] = __float2bfloat16(y - __bfloat162float(hi));
}

// generic: W [K,N] fp32 (layer-strided) -> out [Npad,K] bf16 hi/lo
__global__ void transpose_split_g(const float* __restrict__ W,
                                  __nv_bfloat16* __restrict__ oh,
                                  __nv_bfloat16* __restrict__ ol,
                                  int K, int N,
                                  size_t wstride, size_t ostride) {
    __shared__ float t[32][33];
    int l  = blockIdx.z;
    W  += (size_t)l * wstride;
    oh += (size_t)l * ostride;
    ol += (size_t)l * ostride;
    int n0 = blockIdx.x * 32, k0 = blockIdx.y * 32;
    int tx = threadIdx.x, ty = threadIdx.y;
    #pragma unroll
    for (int i = 0; i < 4; i++) {
        int k = k0 + ty + i * 8;
        int n = n0 + tx;
        t[ty + i * 8][tx] = (n < N) ? W[(size_t)k * N + n] : 0.f;
    }
    __syncthreads();
    #pragma unroll
    for (int i = 0; i < 4; i++) {
        int n = n0 + ty + i * 8;
        int k = k0 + tx;
        float v = t[tx][ty + i * 8];
        __nv_bfloat16 hi = __float2bfloat16(v);
        oh[(size_t)n * K + k] = hi;
        ol[(size_t)n * K + k] = __float2bfloat16(v - __bfloat162float(hi));
    }
}

// fused QKV transpose: wq/wk/wv [L][256][256] -> out [L][768][256]
__global__ void qkv_transpose(const float* __restrict__ wq,
                              const float* __restrict__ wk,
                              const float* __restrict__ wv,
                              __nv_bfloat16* __restrict__ oh,
                              __nv_bfloat16* __restrict__ ol) {
    __shared__ float t[32][33];
    int l  = blockIdx.z;
    int n0 = blockIdx.x * 32, k0 = blockIdx.y * 32;
    const float* W;
    int nb;
    if      (n0 < 256) { W = wq + (size_t)l * Cc * Cc; nb = n0; }
    else if (n0 < 512) { W = wk + (size_t)l * Cc * Cc; nb = n0 - 256; }
    else               { W = wv + (size_t)l * Cc * Cc; nb = n0 - 512; }
    oh += (size_t)l * QKVN * Cc;
    ol += (size_t)l * QKVN * Cc;
    int tx = threadIdx.x, ty = threadIdx.y;
    #pragma unroll
    for (int i = 0; i < 4; i++) {
        int k = k0 + ty + i * 8;
        t[ty + i * 8][tx] = W[(size_t)k * Cc + nb + tx];
    }
    __syncthreads();
    #pragma unroll
    for (int i = 0; i < 4; i++) {
        int n = n0 + ty + i * 8;
        int k = k0 + tx;
        float v = t[tx][ty + i * 8];
        __nv_bfloat16 hi = __float2bfloat16(v);
        oh[(size_t)n * Cc + k] = hi;
        ol[(size_t)n * Cc + k] = __float2bfloat16(v - __bfloat162float(hi));
    }
}

// LayerNorm, outputs bf16 hi/lo split
__global__ void ln_split_kernel(const float* __restrict__ x,
                                const float* __restrict__ g,
                                const float* __restrict__ b,
                                __nv_bfloat16* __restrict__ oh,
                                __nv_bfloat16* __restrict__ ol) {
    int row = blockIdx.x;
    int tid = threadIdx.x;
    float v = x[row * Cc + tid];
    float s = v, s2 = v * v;
    #pragma unroll
    for (int off = 16; off > 0; off >>= 1) {
        s  += __shfl_xor_sync(0xffffffffu, s,  off);
        s2 += __shfl_xor_sync(0xffffffffu, s2, off);
    }
    __shared__ float ss[8], ss2[8];
    __shared__ float mean_s, rstd_s;
    int w = tid >> 5, l = tid & 31;
    if (l == 0) { ss[w] = s; ss2[w] = s2; }
    __syncthreads();
    if (tid == 0) {
        float S = 0.f, S2 = 0.f;
        #pragma unroll
        for (int i = 0; i < 8; i++) { S += ss[i]; S2 += ss2[i]; }
        float m   = S * (1.0f / Cc);
        float var = S2 * (1.0f / Cc) - m * m;
        mean_s = m;
        rstd_s = rsqrtf(var + 1e-5f);
    }
    __syncthreads();
    float y = (v - mean_s) * rstd_s * g[tid] + b[tid];
    __nv_bfloat16 hi = __float2bfloat16(y);
    oh[row * Cc + tid] = hi;
    ol[row * Cc + tid] = __float2bfloat16(y - __bfloat162float(hi));
}

// ================= tcgen05 GEMM (cp.async loads, coalesced epilogue) ========
// Identical to R8-R11 (the winners) — protect the win.
#define GSM_TPTR 0
#define GSM_MBAR 8
#define GSM_AH   1024
#define GSM_AL   (1024 + 16384)
#define GSM_BH   (1024 + 32768)
#define GSM_BL   (1024 + 49152)
#define EPI_PAD  132                       // fp32 row pitch (16B-aligned rows)
#define GSM_SIZE (1024 + 128*EPI_PAD*4)    // 68608 >= 1024+65536 operand area
#define GEMM_IDESC 0x8200490u   // f32 acc, bf16 a/b, N=128, M=128

template<bool BIAS, bool RELU, bool RESID, bool SPLIT>
__global__ __launch_bounds__(256)
void tc_gemm(const __nv_bfloat16* __restrict__ Ah, const __nv_bfloat16* __restrict__ Al,
             const __nv_bfloat16* __restrict__ Bh, const __nv_bfloat16* __restrict__ Bl,
             const float* __restrict__ bias, const float* __restrict__ res,
             float* __restrict__ outf,
             __nv_bfloat16* __restrict__ oh, __nv_bfloat16* __restrict__ ol,
             int Nstore, int K, int ntiles, int Npad) {
#if HAS_TCGEN05
    extern __shared__ char smem[];
    const uint32_t smem_base = smem_to_u32(smem);
    const int tid  = threadIdx.x;
    const int wid  = tid >> 5;
    const int lane = tid & 31;
    const int bm   = blockIdx.y * 128;
    const int bn0  = blockIdx.x * 128 * ntiles;

    if (wid == 0) {
        TCGEN05_ALLOC(smem_base + GSM_TPTR, 128);
        TCGEN05_RELINQ();
    }
    if (tid == 0) MBARRIER_INIT(smem_base + GSM_MBAR, 1);
    __syncthreads();
    uint32_t tmem;
    asm volatile("ld.shared.b32 %0, [%1];" : "=r"(tmem) : "r"(smem_base + GSM_TPTR));

    const uint64_t dAh = make_desc_sw128(smem_base + GSM_AH);
    const uint64_t dAl = make_desc_sw128(smem_base + GSM_AL);
    const uint64_t dBh = make_desc_sw128(smem_base + GSM_BH);
    const uint64_t dBl = make_desc_sw128(smem_base + GSM_BL);

    // per-thread load mapping: 4 iters x one 16B vector per tile buffer
    const int lr = tid >> 3;            // row base 0..31 (+32*i)
    const int lb = (tid & 7) * 16;      // byte offset in 128B row

    const int nchunks = K >> 6;   // K/64
    int cc = 0;                   // global chunk counter (mbarrier parity)

    for (int t = 0; t < ntiles; t++) {
        const int bn = bn0 + t * 128;
        if (bn >= Npad) break;

        for (int c = 0; c < nchunks; c++) {
            const int k0 = c << 6;
            #pragma unroll
            for (int i = 0; i < 4; i++) {
                int r = lr + i * 32;
                uint32_t so = SW128(r * 128 + lb);
                const char* sa = (const char*)(Ah + (size_t)(bm + r) * K + k0) + lb;
                const char* sb = (const char*)(Al + (size_t)(bm + r) * K + k0) + lb;
                const char* sc = (const char*)(Bh + (size_t)(bn + r) * K + k0) + lb;
                const char* sd = (const char*)(Bl + (size_t)(bn + r) * K + k0) + lb;
                cp_async16(smem_base + GSM_AH + so, sa);
                cp_async16(smem_base + GSM_AL + so, sb);
                cp_async16(smem_base + GSM_BH + so, sc);
                cp_async16(smem_base + GSM_BL + so, sd);
            }
            CP_ASYNC_COMMIT();
            CP_ASYNC_WAIT0();
            FENCE_PROXY_ASYNC_SHARED_CTA();
            __syncthreads();

            if (wid == 0 && elect_one_pred()) {
                #pragma unroll
                for (int ks = 0; ks < 4; ks++) {
                    uint64_t oa = (uint64_t)(ks * 2);
                    mma_bf16_ss(tmem, dAh + oa, dBh + oa, GEMM_IDESC, !(c == 0 && ks == 0));
                    mma_bf16_ss(tmem, dAh + oa, dBl + oa, GEMM_IDESC, true);
                    mma_bf16_ss(tmem, dAl + oa, dBh + oa, GEMM_IDESC, true);
                }
                TCGEN05_COMMIT(smem_base + GSM_MBAR);
            }
            // warp 0 polls (no sleep), everyone else joins at the barrier
            if (wid == 0) MBARRIER_POLL(smem_base + GSM_MBAR, cc & 1);
            __syncthreads();
            cc++;
        }
        TCGEN05_FENCE_AFTER();

        // ---- epilogue: transpose through smem, fully coalesced stores ----
        {
            float* eps = (float*)(smem + GSM_AH);   // reuse operand smem
            const int wp   = wid & 3;
            const int colg = (wid >> 2) * 64;
            const int ml   = wp * 32 + lane;        // local row (m)
            #pragma unroll
            for (int half = 0; half < 2; half++) {
                int cb = colg + half * 32;
                uint32_t r[32];
                TCGEN05_LD_32X32B_X32(r, tmem + cb);
                TCGEN05_WAIT_LD();
                #pragma unroll
                for (int j = 0; j < 32; j++)
                    eps[ml * EPI_PAD + cb + j] = __uint_as_float(r[j]);
            }
            TCGEN05_FENCE_BEFORE();
            __syncthreads();

            // 128 rows x 32 float4-cols = 4096 quads; 256 threads x 16 iters.
            #pragma unroll 4
            for (int it = 0; it < 16; it++) {
                int q   = it * 256 + tid;
                int row = q >> 5;
                int c4  = (q & 31) << 2;
                int n   = bn + c4;
                if (n < Nstore) {
                    float4 v = *(const float4*)&eps[row * EPI_PAD + c4];
                    float vals[4] = {v.x, v.y, v.z, v.w};
                    size_t base = (size_t)(bm + row) * Nstore + n;
                    #pragma unroll
                    for (int e = 0; e < 4; e++) {
                        if (BIAS) vals[e] += bias[n + e];
                        if (RELU) vals[e] = fmaxf(vals[e], 0.f);
                    }
                    if (SPLIT) {
                        #pragma unroll
                        for (int e = 0; e < 4; e++) {
                            __nv_bfloat16 hi = __float2bfloat16(vals[e]);
                            oh[base + e] = hi;
                            ol[base + e] = __float2bfloat16(vals[e] - __bfloat162float(hi));
                        }
                    } else {
                        if (RESID) {
                            float4 rv = *(const float4*)&res[base];
                            vals[0] += rv.x; vals[1] += rv.y;
                            vals[2] += rv.z; vals[3] += rv.w;
                        }
                        float4 o;
                        o.x = vals[0]; o.y = vals[1]; o.z = vals[2]; o.w = vals[3];
                        *(float4*)&outf[base] = o;
                    }
                }
            }
            __syncthreads();   // eps dead before next tile's operand loads
        }
    }

    if (tid == 0) MBARRIER_INVAL(smem_base + GSM_MBAR);
    __syncthreads();
    if (wid == 0) TCGEN05_DEALLOC(tmem, 128);
#endif  // HAS_TCGEN05
}

// ================= fused causal attention (bf16 K, 3 CTAs/SM) ===============
// smem: Kst bf16[64][128] (16KB) + Vs f32[128][68] (34KB) + stg[8][512] (16KB)
// stg is a per-warp union: q staging [64][4] during QK, then p staging
// [128][4] for PV (q is dead by then). 67.6KB total -> 3 CTAs/SM (24 warps),
// and K reads are LDS.64 (2 wavefronts/d instead of 4).
#define ATTN_SMEM (64*128*2 + 128*68*4 + 8*512*4)   // 67584 B

__global__ __launch_bounds__(256)
void attn_kernel(const float* __restrict__ qkv,
                 __nv_bfloat16* __restrict__ oh, __nv_bfloat16* __restrict__ ol) {
    extern __shared__ char smc[];
    __nv_bfloat16* Kst = (__nv_bfloat16*)smc;              // [64][128] bf16
    float* Vs  = (float*)(smc + 64*128*2);                 // [128][68]
    float* stg = (float*)(smc + 64*128*2 + 128*68*4);      // [8][512]

    const int b    = blockIdx.x >> 2;
    const int h    = blockIdx.x & 3;
    const int tid  = threadIdx.x;                    // 0..255
    const int lane = tid & 31;
    const int w    = tid >> 5;                       // 0..7

    const float* base_bt = qkv + (size_t)(b * Tt) * QKVN + h * HS;

    // Load K (transposed, bf16) and V: thread pair (row = tid>>1) per row.
    {
        const int row   = tid >> 1;
        const int dhalf = (tid & 1) * 32;
        const float* krow = base_bt + 256 + (size_t)row * QKVN + dhalf;
        const float* vrow = base_bt + 512 + (size_t)row * QKVN + dhalf;
        #pragma unroll
        for (int d4 = 0; d4 < 8; d4++) {
            int d = dhalf + d4 * 4;
            float4 kv = *(const float4*)(krow + d4 * 4);
            Kst[(d + 0) * 128 + row] = __float2bfloat16(kv.x);
            Kst[(d + 1) * 128 + row] = __float2bfloat16(kv.y);
            Kst[(d + 2) * 128 + row] = __float2bfloat16(kv.z);
            Kst[(d + 3) * 128 + row] = __float2bfloat16(kv.w);
            *(float4*)&Vs[row * 68 + d] = *(const float4*)(vrow + d4 * 4);
        }
    }
    __syncthreads();

    const float scale = 0.0625f;  // 256^-0.5
    float* sw = stg + w * 512;    // union: q [d][4] then p [kk][4]

    for (int batch = 0; batch < 4; batch++) {
        int qr[4];
        #pragma unroll
        for (int i = 0; i < 4; i++) qr[i] = (batch * 4 + i) * 8 + w;

        // stage 4 q rows: sw[d*4 + i]
        #pragma unroll
        for (int i = 0; i < 4; i++) {
            const float* qrow = base_bt + (size_t)qr[i] * QKVN;
            sw[lane * 4 + i]        = qrow[lane];
            sw[(lane + 32) * 4 + i] = qrow[lane + 32];
        }
        __syncwarp();

        // scores: s[i][e] for key kk = 4*lane + e
        float s[4][4];
        #pragma unroll
        for (int i = 0; i < 4; i++)
            #pragma unroll
            for (int e = 0; e < 4; e++) s[i][e] = 0.f;

        #pragma unroll 8
        for (int d = 0; d < 64; d++) {
            // 4 bf16 keys in one LDS.64
            __nv_bfloat162 k01 = *(const __nv_bfloat162*)&Kst[d * 128 + 4 * lane];
            __nv_bfloat162 k23 = *(const __nv_bfloat162*)&Kst[d * 128 + 4 * lane + 2];
            float2 f01 = __bfloat1622float2(k01);
            float2 f23 = __bfloat1622float2(k23);
            float kx = f01.x, ky = f01.y, kz = f23.x, kw = f23.y;
            float4 q4 = *(const float4*)&sw[d * 4];   // one broadcast: rows 0-3
            s[0][0] = fmaf(q4.x, kx, s[0][0]); s[0][1] = fmaf(q4.x, ky, s[0][1]);
            s[0][2] = fmaf(q4.x, kz, s[0][2]); s[0][3] = fmaf(q4.x, kw, s[0][3]);
            s[1][0] = fmaf(q4.y, kx, s[1][0]); s[1][1] = fmaf(q4.y, ky, s[1][1]);
            s[1][2] = fmaf(q4.y, kz, s[1][2]); s[1][3] = fmaf(q4.y, kw, s[1][3]);
            s[2][0] = fmaf(q4.z, kx, s[2][0]); s[2][1] = fmaf(q4.z, ky, s[2][1]);
            s[2][2] = fmaf(q4.z, kz, s[2][2]); s[2][3] = fmaf(q4.z, kw, s[2][3]);
            s[3][0] = fmaf(q4.w, kx, s[3][0]); s[3][1] = fmaf(q4.w, ky, s[3][1]);
            s[3][2] = fmaf(q4.w, kz, s[3][2]); s[3][3] = fmaf(q4.w, kw, s[3][3]);
        }
        __syncwarp();   // q reads done before p overwrites sw

        // softmax per row; p kept in regs, then packed stores sw[kk*4 + i]
        float p[4][4];
        #pragma unroll
        for (int i = 0; i < 4; i++) {
            float e[4];
            float mx = -1e30f;
            #pragma unroll
            for (int ee = 0; ee < 4; ee++) {
                int kk = 4 * lane + ee;
                float sv = s[i][ee] * scale;
                s[i][ee] = sv;
                if (kk <= qr[i]) mx = fmaxf(mx, sv);
            }
            #pragma unroll
            for (int off = 16; off > 0; off >>= 1)
                mx = fmaxf(mx, __shfl_xor_sync(0xffffffffu, mx, off));
            float sum = 0.f;
            #pragma unroll
            for (int ee = 0; ee < 4; ee++) {
                int kk = 4 * lane + ee;
                e[ee] = (kk <= qr[i]) ? __expf(s[i][ee] - mx) : 0.f;
                sum += e[ee];
            }
            #pragma unroll
            for (int off = 16; off > 0; off >>= 1)
                sum += __shfl_xor_sync(0xffffffffu, sum, off);
            float rs = 1.0f / sum;
            #pragma unroll
            for (int ee = 0; ee < 4; ee++) p[i][ee] = e[ee] * rs;
        }
        // sw[(4*lane+e)*4 + i] : per lane a contiguous 64B block (4x STS.128)
        #pragma unroll
        for (int ee = 0; ee < 4; ee++) {
            float4 pv;
            pv.x = p[0][ee]; pv.y = p[1][ee]; pv.z = p[2][ee]; pv.w = p[3][ee];
            *(float4*)&sw[(4 * lane + ee) * 4] = pv;
        }
        __syncwarp();

        // PV: lane owns dims d0 = 2*lane, d1 = 2*lane+1
        float o[4][2];
        #pragma unroll
        for (int i = 0; i < 4; i++) { o[i][0] = 0.f; o[i][1] = 0.f; }
        const int kmax = qr[3];   // largest row in batch; masked p are 0
        #pragma unroll 4
        for (int kk = 0; kk <= kmax; kk++) {
            float2 v = *(const float2*)&Vs[kk * 68 + 2 * lane];
            float4 p4 = *(const float4*)&sw[kk * 4];  // one broadcast: rows 0-3
            o[0][0] = fmaf(p4.x, v.x, o[0][0]); o[0][1] = fmaf(p4.x, v.y, o[0][1]);
            o[1][0] = fmaf(p4.y, v.x, o[1][0]); o[1][1] = fmaf(p4.y, v.y, o[1][1]);
            o[2][0] = fmaf(p4.z, v.x, o[2][0]); o[2][1] = fmaf(p4.z, v.y, o[2][1]);
            o[3][0] = fmaf(p4.w, v.x, o[3][0]); o[3][1] = fmaf(p4.w, v.y, o[3][1]);
        }

        #pragma unroll
        for (int i = 0; i < 4; i++) {
            size_t obase = (size_t)(b * Tt + qr[i]) * Cc + h * HS + 2 * lane;
            __nv_bfloat16 h0 = __float2bfloat16(o[i][0]);
            __nv_bfloat16 h1 = __float2bfloat16(o[i][1]);
            oh[obase]     = h0;
            oh[obase + 1] = h1;
            ol[obase]     = __float2bfloat16(o[i][0] - __bfloat162float(h0));
            ol[obase + 1] = __float2bfloat16(o[i][1] - __bfloat162float(h1));
        }
        __syncwarp();   // sw reused next batch
    }
}

// ================= launch ===================================================
extern "C" void kernel_launch(void* const* d_in, const int* in_sizes, int n_in,
                              void* d_out, int out_size) {
    const int*   idx   = (const int*)  d_in[0];
    const float* tok   = (const float*)d_in[1];
    const float* pos   = (const float*)d_in[2];
    const float* ln1g  = (const float*)d_in[3];
    const float* ln1b  = (const float*)d_in[4];
    const float* wq    = (const float*)d_in[5];
    const float* wk    = (const float*)d_in[6];
    const float* wv    = (const float*)d_in[7];
    const float* projw = (const float*)d_in[8];
    const float* projb = (const float*)d_in[9];
    const float* ln2g  = (const float*)d_in[10];
    const float* ln2b  = (const float*)d_in[11];
    const float* w1    = (const float*)d_in[12];
    const float* b1    = (const float*)d_in[13];
    const float* w2    = (const float*)d_in[14];
    const float* b2    = (const float*)d_in[15];
    const float* lnfg  = (const float*)d_in[16];
    const float* lnfb  = (const float*)d_in[17];
    const float* lmw   = (const float*)d_in[18];
    const float* lmb   = (const float*)d_in[19];
    float* out = (float*)d_out;

    float *x, *qkv;
    __nv_bfloat16 *hh, *hl, *ah, *al, *fh, *fl;
    __nv_bfloat16 *qkvTh, *qkvTl, *pTh, *pTl;
    __nv_bfloat16 *w1Th, *w1Tl, *w2Th, *w2Tl, *lmTh, *lmTl;
    cudaGetSymbolAddress((void**)&x,   g_x);
    cudaGetSymbolAddress((void**)&qkv, g_qkv);
    cudaGetSymbolAddress((void**)&hh, g_hh);  cudaGetSymbolAddress((void**)&hl, g_hl);
    cudaGetSymbolAddress((void**)&ah, g_ah);  cudaGetSymbolAddress((void**)&al, g_al);
    cudaGetSymbolAddress((void**)&fh, g_fh);  cudaGetSymbolAddress((void**)&fl, g_fl);
    cudaGetSymbolAddress((void**)&qkvTh, g_qkvT_h); cudaGetSymbolAddress((void**)&qkvTl, g_qkvT_l);
    cudaGetSymbolAddress((void**)&pTh,  g_pT_h);    cudaGetSymbolAddress((void**)&pTl,  g_pT_l);
    cudaGetSymbolAddress((void**)&w1Th, g_w1T_h);   cudaGetSymbolAddress((void**)&w1Tl, g_w1T_l);
    cudaGetSymbolAddress((void**)&w2Th, g_w2T_h);   cudaGetSymbolAddress((void**)&w2Tl, g_w2T_l);
    cudaGetSymbolAddress((void**)&lmTh, g_lmT_h);   cudaGetSymbolAddress((void**)&lmTl, g_lmT_l);

    cudaFuncSetAttribute(attn_kernel,
                         cudaFuncAttributeMaxDynamicSharedMemorySize, ATTN_SMEM);
    cudaFuncSetAttribute(tc_gemm<false,false,false,false>,
                         cudaFuncAttributeMaxDynamicSharedMemorySize, GSM_SIZE);
    cudaFuncSetAttribute(tc_gemm<true,false,true,false>,
                         cudaFuncAttributeMaxDynamicSharedMemorySize, GSM_SIZE);
    cudaFuncSetAttribute(tc_gemm<true,true,false,true>,
                         cudaFuncAttributeMaxDynamicSharedMemorySize, GSM_SIZE);
    cudaFuncSetAttribute(tc_gemm<true,false,false,false>,
                         cudaFuncAttributeMaxDynamicSharedMemorySize, GSM_SIZE);

    dim3 tb(32, 8);
    const dim3 gC(Cc / 128,   BT / 128);   // N=256
    const dim3 gQ(QKVN / 128, BT / 128);   // N=768
    const dim3 gF(DFF / 128,  BT / 128);   // N=1024
    const dim3 gV(VPAD / 512, BT / 128);   // LM head: 20 x 128, 4 N-tiles/CTA

    // Launch order: index 3 is the profiled launch -> attn_kernel.
    qkv_transpose<<<dim3(QKVN/32, Cc/32, Ll), tb>>>(wq, wk, wv, qkvTh, qkvTl);      // 0
    embed_ln_kernel<<<BT, 256>>>(idx, tok, pos, ln1g, ln1b, x, hh, hl);             // 1
    tc_gemm<false,false,false,false><<<gQ, 256, GSM_SIZE>>>(                        // 2
        hh, hl, qkvTh, qkvTl, nullptr, nullptr, qkv, nullptr, nullptr,
        QKVN, Cc, 1, QKVN);
    attn_kernel<<<Bb * Hh, 256, ATTN_SMEM>>>(qkv, ah, al);                          // 3 (PROFILED)
    transpose_split_g<<<dim3(Cc/32, Cc/32, Ll), tb>>>(projw, pTh, pTl, Cc, Cc,
                                                      (size_t)Cc*Cc, (size_t)Cc*Cc);
    transpose_split_g<<<dim3(DFF/32, Cc/32, Ll), tb>>>(w1, w1Th, w1Tl, Cc, DFF,
                                                       (size_t)Cc*DFF, (size_t)Cc*DFF);
    transpose_split_g<<<dim3(Cc/32, DFF/32, Ll), tb>>>(w2, w2Th, w2Tl, DFF, Cc,
                                                       (size_t)Cc*DFF, (size_t)Cc*DFF);
    transpose_split_g<<<dim3(VPAD/32, Cc/32, 1), tb>>>(lmw, lmTh, lmTl, Cc, Vv, 0, 0);

    for (int l = 0; l < Ll; l++) {
        size_t oQ = (size_t)l * QKVN * Cc;
        size_t o2 = (size_t)l * Cc * Cc;
        size_t oF = (size_t)l * Cc * DFF;

        if (l > 0) {
            ln_split_kernel<<<BT, 256>>>(x, ln1g + l*Cc, ln1b + l*Cc, hh, hl);
            tc_gemm<false,false,false,false><<<gQ, 256, GSM_SIZE>>>(
                hh, hl, qkvTh + oQ, qkvTl + oQ, nullptr, nullptr, qkv,
                nullptr, nullptr, QKVN, Cc, 1, QKVN);
            attn_kernel<<<Bb * Hh, 256, ATTN_SMEM>>>(qkv, ah, al);
        }

        tc_gemm<true,false,true,false><<<gC, 256, GSM_SIZE>>>(
            ah, al, pTh + o2, pTl + o2, projb + l*Cc, x, x, nullptr, nullptr,
            Cc, Cc, 1, Cc);

        ln_split_kernel<<<BT, 256>>>(x, ln2g + l*Cc, ln2b + l*Cc, hh, hl);

        tc_gemm<true,true,false,true><<<gF, 256, GSM_SIZE>>>(
            hh, hl, w1Th + oF, w1Tl + oF, b1 + l*DFF, nullptr, nullptr, fh, fl,
            DFF, Cc, 1, DFF);

        tc_gemm<true,false,true,false><<<gC, 256, GSM_SIZE>>>(
            fh, fl, w2Th + oF, w2Tl + oF, b2 + l*Cc, x, x, nullptr, nullptr,
            Cc, DFF, 1, Cc);
    }

    ln_split_kernel<<<BT, 256>>>(x, lnfg, lnfb, hh, hl);

    tc_gemm<true,false,false,false><<<gV, 256, GSM_SIZE>>>(
        hh, hl, lmTh, lmTl, lmb, nullptr, out, nullptr, nullptr,
        Vv, Cc, 4, VPAD);
}

// round 13
// speedup vs baseline: 1.0528x; 1.0528x over previous
#include <cuda_runtime.h>
#include <cuda_bf16.h>
#include <math.h>
#include <cstdint>

// tcgen05 is only legal on arch-specific targets (sm_103a / sm_100a).
// The harness's nvcc also runs a generic compute_103 PTX pass; guard so that
// pass compiles empty bodies (the sm_103a cubin is what actually runs).
#if !defined(__CUDA_ARCH__) || defined(__CUDA_ARCH_FEAT_SM103_ALL) || \
    defined(__CUDA_ARCH_FEAT_SM100_ALL) || defined(__CUDA_ARCH_FEAT_SM101_ALL)
#define HAS_TCGEN05 1
#else
#define HAS_TCGEN05 0
#endif

// Problem dims
#define Bb   128
#define Tt   128
#define Cc   256
#define Hh   4
#define HS   64
#define Ll   6
#define DFF  1024
#define Vv   10000
#define BT   (Bb*Tt)   // 16384
#define VPAD 10240     // 80*128 (LM head padded to 4-tile groups)
#define QKVN 768

// ================= PTX helpers (sm_103a tcgen05) ===========================
__device__ __forceinline__ uint32_t smem_to_u32(const void* p) {
    uint32_t a;
    asm("{ .reg .u64 t; cvta.to.shared.u64 t, %1; cvt.u32.u64 %0, t; }"
        : "=r"(a) : "l"(p));
    return a;
}

#if HAS_TCGEN05
__device__ __forceinline__ uint32_t elect_one_pred() {
    uint32_t pred;
    asm volatile(
        "{\n\t.reg .pred p;\n\telect.sync _|p, 0xFFFFFFFF;\n\t"
        "selp.b32 %0, 1, 0, p;\n\t}"
        : "=r"(pred));
    return pred;
}
#define TCGEN05_ALLOC(smem_addr, nCols) \
    asm volatile("tcgen05.alloc.cta_group::1.sync.aligned.shared::cta.b32 [%0], %1;" \
        :: "r"((uint32_t)(smem_addr)), "r"((uint32_t)(nCols)) : "memory")
#define TCGEN05_DEALLOC(tmem_addr, nCols) \
    asm volatile("tcgen05.dealloc.cta_group::1.sync.aligned.b32 %0, %1;" \
        :: "r"(tmem_addr), "r"((uint32_t)(nCols)))
#define TCGEN05_RELINQ() \
    asm volatile("tcgen05.relinquish_alloc_permit.cta_group::1.sync.aligned;")
#define TCGEN05_COMMIT(mbar) \
    asm volatile("tcgen05.commit.cta_group::1.mbarrier::arrive::one.shared::cluster.b64 [%0];" \
        :: "r"((uint32_t)(mbar)) : "memory")
#define TCGEN05_FENCE_BEFORE() \
    asm volatile("tcgen05.fence::before_thread_sync;" ::: "memory")
#define TCGEN05_FENCE_AFTER() \
    asm volatile("tcgen05.fence::after_thread_sync;" ::: "memory")
#define TCGEN05_WAIT_LD() \
    asm volatile("tcgen05.wait::ld.sync.aligned;" ::: "memory")
#define FENCE_PROXY_ASYNC_SHARED_CTA() \
    asm volatile("fence.proxy.async.shared::cta;" ::: "memory")
#define MBARRIER_INIT(mbar, count) \
    asm volatile("mbarrier.init.shared.b64 [%0], %1;" \
        :: "r"((uint32_t)(mbar)), "r"((uint32_t)(count)) : "memory")
#define MBARRIER_INVAL(mbar) \
    asm volatile("mbarrier.inval.shared.b64 [%0];" :: "r"((uint32_t)(mbar)) : "memory")
// Non-blocking poll: mbarrier.test_wait in a spin loop, no sleep.
#define MBARRIER_POLL(mbar, parity) do { \
    uint32_t _mbar = (uint32_t)(mbar); \
    uint32_t _par  = (uint32_t)(parity); \
    uint32_t _done = 0; \
    while (!_done) { \
        asm volatile( \
            "{\n\t.reg .pred p;\n\t" \
            "mbarrier.test_wait.parity.acquire.cta.shared::cta.b64 p, [%1], %2;\n\t" \
            "selp.b32 %0, 1, 0, p;\n\t}" \
            : "=r"(_done) : "r"(_mbar), "r"(_par) : "memory"); \
    } \
} while (0)
// Async 16B copy global->shared (LDGSTS). Register-free, deep MLP.
__device__ __forceinline__ void cp_async16(uint32_t dst, const void* src) {
    asm volatile("cp.async.cg.shared.global [%0], [%1], 16;"
        :: "r"(dst), "l"(src) : "memory");
}
#define CP_ASYNC_COMMIT() asm volatile("cp.async.commit_group;" ::: "memory")
#define CP_ASYNC_WAIT0()  asm volatile("cp.async.wait_group 0;" ::: "memory")
#define TCGEN05_LD_32X32B_X32(r, tmem_addr) \
    asm volatile( \
        "tcgen05.ld.sync.aligned.32x32b.x32.b32 " \
        "{%0, %1, %2, %3, %4, %5, %6, %7, " \
        " %8, %9, %10, %11, %12, %13, %14, %15, " \
        " %16, %17, %18, %19, %20, %21, %22, %23, " \
        " %24, %25, %26, %27, %28, %29, %30, %31}, [%32];" \
        : "=r"((r)[0]),  "=r"((r)[1]),  "=r"((r)[2]),  "=r"((r)[3]), \
          "=r"((r)[4]),  "=r"((r)[5]),  "=r"((r)[6]),  "=r"((r)[7]), \
          "=r"((r)[8]),  "=r"((r)[9]),  "=r"((r)[10]), "=r"((r)[11]), \
          "=r"((r)[12]), "=r"((r)[13]), "=r"((r)[14]), "=r"((r)[15]), \
          "=r"((r)[16]), "=r"((r)[17]), "=r"((r)[18]), "=r"((r)[19]), \
          "=r"((r)[20]), "=r"((r)[21]), "=r"((r)[22]), "=r"((r)[23]), \
          "=r"((r)[24]), "=r"((r)[25]), "=r"((r)[26]), "=r"((r)[27]), \
          "=r"((r)[28]), "=r"((r)[29]), "=r"((r)[30]), "=r"((r)[31]) \
        : "r"(tmem_addr))

// cg1 bf16 SS MMA (A in SMEM, B in SMEM), fp32 accumulate
__device__ __forceinline__ void mma_bf16_ss(uint32_t d, uint64_t a, uint64_t b,
                                            uint32_t idesc, bool en) {
    uint32_t e = en ? 1u : 0u;
    asm volatile(
        "{\n\t.reg .pred p;\n\t"
        "setp.ne.u32 p, %5, 0;\n\t"
        "tcgen05.mma.cta_group::1.kind::f16 [%0], %1, %2, %3, {%4, %4, %4, %4}, p;\n\t}"
        :: "r"(d), "l"(a), "l"(b), "r"(idesc), "r"(0u), "r"(e)
        : "memory");
}
#endif  // HAS_TCGEN05

// 64-bit SMEM descriptor: SW128, Blackwell v1, LBO=1, SBO=64 (K-major 128B rows)
static __device__ __forceinline__ uint64_t make_desc_sw128(uint32_t addr) {
    const uint64_t base =
        (uint64_t(2)  << 61) | (uint64_t(1) << 46) |
        (uint64_t(64) << 32) | (uint64_t(1) << 16);
    return base | ((uint64_t)(addr >> 4) & 0x3FFF);
}
#define SW128(bo) ((bo) ^ (((bo) >> 3) & 0x70))

// ================= scratch (device globals) ================================
__device__ __align__(16) float g_x  [BT*Cc];
__device__ __align__(16) float g_qkv[BT*QKVN];
// bf16 hi/lo activations
__device__ __align__(16) __nv_bfloat16 g_hh[BT*Cc],  g_hl[BT*Cc];
__device__ __align__(16) __nv_bfloat16 g_ah[BT*Cc],  g_al[BT*Cc];
__device__ __align__(16) __nv_bfloat16 g_fh[BT*DFF], g_fl[BT*DFF];
// transposed+split weights: [N(pad), K] K-major
__device__ __align__(16) __nv_bfloat16 g_qkvT_h[Ll*QKVN*Cc], g_qkvT_l[Ll*QKVN*Cc];
__device__ __align__(16) __nv_bfloat16 g_pT_h [Ll*Cc*Cc],    g_pT_l [Ll*Cc*Cc];
__device__ __align__(16) __nv_bfloat16 g_w1T_h[Ll*DFF*Cc],   g_w1T_l[Ll*DFF*Cc];
__device__ __align__(16) __nv_bfloat16 g_w2T_h[Ll*Cc*DFF],   g_w2T_l[Ll*Cc*DFF];
__device__ __align__(16) __nv_bfloat16 g_lmT_h[VPAD*Cc],     g_lmT_l[VPAD*Cc];

// ================= small kernels ===========================================
// Fused embedding + LN1(layer 0): one block per row. Writes x AND hh/hl.
__global__ void embed_ln_kernel(const int* __restrict__ idx,
                                const float* __restrict__ tok,
                                const float* __restrict__ pos,
                                const float* __restrict__ g,
                                const float* __restrict__ b,
                                float* __restrict__ x,
                                __nv_bfloat16* __restrict__ oh,
                                __nv_bfloat16* __restrict__ ol) {
    int row = blockIdx.x;
    int tid = threadIdx.x;
    int t   = row & (Tt - 1);
    float v = tok[idx[row] * Cc + tid] + pos[t * Cc + tid];
    x[row * Cc + tid] = v;
    float s = v, s2 = v * v;
    #pragma unroll
    for (int off = 16; off > 0; off >>= 1) {
        s  += __shfl_xor_sync(0xffffffffu, s,  off);
        s2 += __shfl_xor_sync(0xffffffffu, s2, off);
    }
    __shared__ float ss[8], ss2[8];
    __shared__ float mean_s, rstd_s;
    int w = tid >> 5, l = tid & 31;
    if (l == 0) { ss[w] = s; ss2[w] = s2; }
    __syncthreads();
    if (tid == 0) {
        float S = 0.f, S2 = 0.f;
        #pragma unroll
        for (int i = 0; i < 8; i++) { S += ss[i]; S2 += ss2[i]; }
        float m   = S * (1.0f / Cc);
        float var = S2 * (1.0f / Cc) - m * m;
        mean_s = m;
        rstd_s = rsqrtf(var + 1e-5f);
    }
    __syncthreads();
    float y = (v - mean_s) * rstd_s * g[tid] + b[tid];
    __nv_bfloat16 hi = __float2bfloat16(y);
    oh[row * Cc + tid] = hi;
    ol[row * Cc + tid] = __float2bfloat16(y - __bfloat162float(hi));
}

// generic: W [K,N] fp32 (layer-strided) -> out [Npad,K] bf16 hi/lo
__global__ void transpose_split_g(const float* __restrict__ W,
                                  __nv_bfloat16* __restrict__ oh,
                                  __nv_bfloat16* __restrict__ ol,
                                  int K, int N,
                                  size_t wstride, size_t ostride) {
    __shared__ float t[32][33];
    int l  = blockIdx.z;
    W  += (size_t)l * wstride;
    oh += (size_t)l * ostride;
    ol += (size_t)l * ostride;
    int n0 = blockIdx.x * 32, k0 = blockIdx.y * 32;
    int tx = threadIdx.x, ty = threadIdx.y;
    #pragma unroll
    for (int i = 0; i < 4; i++) {
        int k = k0 + ty + i * 8;
        int n = n0 + tx;
        t[ty + i * 8][tx] = (n < N) ? W[(size_t)k * N + n] : 0.f;
    }
    __syncthreads();
    #pragma unroll
    for (int i = 0; i < 4; i++) {
        int n = n0 + ty + i * 8;
        int k = k0 + tx;
        float v = t[tx][ty + i * 8];
        __nv_bfloat16 hi = __float2bfloat16(v);
        oh[(size_t)n * K + k] = hi;
        ol[(size_t)n * K + k] = __float2bfloat16(v - __bfloat162float(hi));
    }
}

// fused QKV transpose: wq/wk/wv [L][256][256] -> out [L][768][256]
__global__ void qkv_transpose(const float* __restrict__ wq,
                              const float* __restrict__ wk,
                              const float* __restrict__ wv,
                              __nv_bfloat16* __restrict__ oh,
                              __nv_bfloat16* __restrict__ ol) {
    __shared__ float t[32][33];
    int l  = blockIdx.z;
    int n0 = blockIdx.x * 32, k0 = blockIdx.y * 32;
    const float* W;
    int nb;
    if      (n0 < 256) { W = wq + (size_t)l * Cc * Cc; nb = n0; }
    else if (n0 < 512) { W = wk + (size_t)l * Cc * Cc; nb = n0 - 256; }
    else               { W = wv + (size_t)l * Cc * Cc; nb = n0 - 512; }
    oh += (size_t)l * QKVN * Cc;
    ol += (size_t)l * QKVN * Cc;
    int tx = threadIdx.x, ty = threadIdx.y;
    #pragma unroll
    for (int i = 0; i < 4; i++) {
        int k = k0 + ty + i * 8;
        t[ty + i * 8][tx] = W[(size_t)k * Cc + nb + tx];
    }
    __syncthreads();
    #pragma unroll
    for (int i = 0; i < 4; i++) {
        int n = n0 + ty + i * 8;
        int k = k0 + tx;
        float v = t[tx][ty + i * 8];
        __nv_bfloat16 hi = __float2bfloat16(v);
        oh[(size_t)n * Cc + k] = hi;
        ol[(size_t)n * Cc + k] = __float2bfloat16(v - __bfloat162float(hi));
    }
}

// LayerNorm, outputs bf16 hi/lo split
__global__ void ln_split_kernel(const float* __restrict__ x,
                                const float* __restrict__ g,
                                const float* __restrict__ b,
                                __nv_bfloat16* __restrict__ oh,
                                __nv_bfloat16* __restrict__ ol) {
    int row = blockIdx.x;
    int tid = threadIdx.x;
    float v = x[row * Cc + tid];
    float s = v, s2 = v * v;
    #pragma unroll
    for (int off = 16; off > 0; off >>= 1) {
        s  += __shfl_xor_sync(0xffffffffu, s,  off);
        s2 += __shfl_xor_sync(0xffffffffu, s2, off);
    }
    __shared__ float ss[8], ss2[8];
    __shared__ float mean_s, rstd_s;
    int w = tid >> 5, l = tid & 31;
    if (l == 0) { ss[w] = s; ss2[w] = s2; }
    __syncthreads();
    if (tid == 0) {
        float S = 0.f, S2 = 0.f;
        #pragma unroll
        for (int i = 0; i < 8; i++) { S += ss[i]; S2 += ss2[i]; }
        float m   = S * (1.0f / Cc);
        float var = S2 * (1.0f / Cc) - m * m;
        mean_s = m;
        rstd_s = rsqrtf(var + 1e-5f);
    }
    __syncthreads();
    float y = (v - mean_s) * rstd_s * g[tid] + b[tid];
    __nv_bfloat16 hi = __float2bfloat16(y);
    oh[row * Cc + tid] = hi;
    ol[row * Cc + tid] = __float2bfloat16(y - __bfloat162float(hi));
}

// ================= tcgen05 GEMM (cp.async loads, coalesced epilogue) ========
// Identical to R8-R11 (the winners) — protect the win.
#define GSM_TPTR 0
#define GSM_MBAR 8
#define GSM_AH   1024
#define GSM_AL   (1024 + 16384)
#define GSM_BH   (1024 + 32768)
#define GSM_BL   (1024 + 49152)
#define EPI_PAD  132                       // fp32 row pitch (16B-aligned rows)
#define GSM_SIZE (1024 + 128*EPI_PAD*4)    // 68608 >= 1024+65536 operand area
#define GEMM_IDESC 0x8200490u   // f32 acc, bf16 a/b, N=128, M=128

template<bool BIAS, bool RELU, bool RESID, bool SPLIT>
__global__ __launch_bounds__(256)
void tc_gemm(const __nv_bfloat16* __restrict__ Ah, const __nv_bfloat16* __restrict__ Al,
             const __nv_bfloat16* __restrict__ Bh, const __nv_bfloat16* __restrict__ Bl,
             const float* __restrict__ bias, const float* __restrict__ res,
             float* __restrict__ outf,
             __nv_bfloat16* __restrict__ oh, __nv_bfloat16* __restrict__ ol,
             int Nstore, int K, int ntiles, int Npad) {
#if HAS_TCGEN05
    extern __shared__ char smem[];
    const uint32_t smem_base = smem_to_u32(smem);
    const int tid  = threadIdx.x;
    const int wid  = tid >> 5;
    const int lane = tid & 31;
    const int bm   = blockIdx.y * 128;
    const int bn0  = blockIdx.x * 128 * ntiles;

    if (wid == 0) {
        TCGEN05_ALLOC(smem_base + GSM_TPTR, 128);
        TCGEN05_RELINQ();
    }
    if (tid == 0) MBARRIER_INIT(smem_base + GSM_MBAR, 1);
    __syncthreads();
    uint32_t tmem;
    asm volatile("ld.shared.b32 %0, [%1];" : "=r"(tmem) : "r"(smem_base + GSM_TPTR));

    const uint64_t dAh = make_desc_sw128(smem_base + GSM_AH);
    const uint64_t dAl = make_desc_sw128(smem_base + GSM_AL);
    const uint64_t dBh = make_desc_sw128(smem_base + GSM_BH);
    const uint64_t dBl = make_desc_sw128(smem_base + GSM_BL);

    // per-thread load mapping: 4 iters x one 16B vector per tile buffer
    const int lr = tid >> 3;            // row base 0..31 (+32*i)
    const int lb = (tid & 7) * 16;      // byte offset in 128B row

    const int nchunks = K >> 6;   // K/64
    int cc = 0;                   // global chunk counter (mbarrier parity)

    for (int t = 0; t < ntiles; t++) {
        const int bn = bn0 + t * 128;
        if (bn >= Npad) break;

        for (int c = 0; c < nchunks; c++) {
            const int k0 = c << 6;
            #pragma unroll
            for (int i = 0; i < 4; i++) {
                int r = lr + i * 32;
                uint32_t so = SW128(r * 128 + lb);
                const char* sa = (const char*)(Ah + (size_t)(bm + r) * K + k0) + lb;
                const char* sb = (const char*)(Al + (size_t)(bm + r) * K + k0) + lb;
                const char* sc = (const char*)(Bh + (size_t)(bn + r) * K + k0) + lb;
                const char* sd = (const char*)(Bl + (size_t)(bn + r) * K + k0) + lb;
                cp_async16(smem_base + GSM_AH + so, sa);
                cp_async16(smem_base + GSM_AL + so, sb);
                cp_async16(smem_base + GSM_BH + so, sc);
                cp_async16(smem_base + GSM_BL + so, sd);
            }
            CP_ASYNC_COMMIT();
            CP_ASYNC_WAIT0();
            FENCE_PROXY_ASYNC_SHARED_CTA();
            __syncthreads();

            if (wid == 0 && elect_one_pred()) {
                #pragma unroll
                for (int ks = 0; ks < 4; ks++) {
                    uint64_t oa = (uint64_t)(ks * 2);
                    mma_bf16_ss(tmem, dAh + oa, dBh + oa, GEMM_IDESC, !(c == 0 && ks == 0));
                    mma_bf16_ss(tmem, dAh + oa, dBl + oa, GEMM_IDESC, true);
                    mma_bf16_ss(tmem, dAl + oa, dBh + oa, GEMM_IDESC, true);
                }
                TCGEN05_COMMIT(smem_base + GSM_MBAR);
            }
            // warp 0 polls (no sleep), everyone else joins at the barrier
            if (wid == 0) MBARRIER_POLL(smem_base + GSM_MBAR, cc & 1);
            __syncthreads();
            cc++;
        }
        TCGEN05_FENCE_AFTER();

        // ---- epilogue: transpose through smem, fully coalesced stores ----
        {
            float* eps = (float*)(smem + GSM_AH);   // reuse operand smem
            const int wp   = wid & 3;
            const int colg = (wid >> 2) * 64;
            const int ml   = wp * 32 + lane;        // local row (m)
            #pragma unroll
            for (int half = 0; half < 2; half++) {
                int cb = colg + half * 32;
                uint32_t r[32];
                TCGEN05_LD_32X32B_X32(r, tmem + cb);
                TCGEN05_WAIT_LD();
                #pragma unroll
                for (int j = 0; j < 32; j++)
                    eps[ml * EPI_PAD + cb + j] = __uint_as_float(r[j]);
            }
            TCGEN05_FENCE_BEFORE();
            __syncthreads();

            // 128 rows x 32 float4-cols = 4096 quads; 256 threads x 16 iters.
            #pragma unroll 4
            for (int it = 0; it < 16; it++) {
                int q   = it * 256 + tid;
                int row = q >> 5;
                int c4  = (q & 31) << 2;
                int n   = bn + c4;
                if (n < Nstore) {
                    float4 v = *(const float4*)&eps[row * EPI_PAD + c4];
                    float vals[4] = {v.x, v.y, v.z, v.w};
                    size_t base = (size_t)(bm + row) * Nstore + n;
                    #pragma unroll
                    for (int e = 0; e < 4; e++) {
                        if (BIAS) vals[e] += bias[n + e];
                        if (RELU) vals[e] = fmaxf(vals[e], 0.f);
                    }
                    if (SPLIT) {
                        #pragma unroll
                        for (int e = 0; e < 4; e++) {
                            __nv_bfloat16 hi = __float2bfloat16(vals[e]);
                            oh[base + e] = hi;
                            ol[base + e] = __float2bfloat16(vals[e] - __bfloat162float(hi));
                        }
                    } else {
                        if (RESID) {
                            float4 rv = *(const float4*)&res[base];
                            vals[0] += rv.x; vals[1] += rv.y;
                            vals[2] += rv.z; vals[3] += rv.w;
                        }
                        float4 o;
                        o.x = vals[0]; o.y = vals[1]; o.z = vals[2]; o.w = vals[3];
                        *(float4*)&outf[base] = o;
                    }
                }
            }
            __syncthreads();   // eps dead before next tile's operand loads
        }
    }

    if (tid == 0) MBARRIER_INVAL(smem_base + GSM_MBAR);
    __syncthreads();
    if (wid == 0) TCGEN05_DEALLOC(tmem, 128);
#endif  // HAS_TCGEN05
}

// ================= fused causal attention (8-row passes, fp32 K) ============
// smem: Kst[64][128] (32KB) + Vs[128][68] (34KB) + stg[8][1024] (32KB) = 98KB
// Each warp runs 2 passes of 8 consecutive rows (pass*64 + w*8 + i): one K
// read feeds 32 FMAs, one V read feeds 16 FMAs. q staged [d][8], p staged
// [kk][8] (both read as 2 LDS.128 broadcasts). Key mapping kk = lane + 32e.
#define ATTN_SMEM ((64*128 + 128*68 + 8*1024) * 4)   // 100352 B

__global__ __launch_bounds__(256)
void attn_kernel(const float* __restrict__ qkv,
                 __nv_bfloat16* __restrict__ oh, __nv_bfloat16* __restrict__ ol) {
    extern __shared__ float sm[];
    float* Kst = sm;                                 // [64][128] d-major
    float* Vs  = sm + 64 * 128;                      // [128][68]
    float* stg = sm + 64 * 128 + 128 * 68;           // [8][1024] union q/p

    const int b    = blockIdx.x >> 2;
    const int h    = blockIdx.x & 3;
    const int tid  = threadIdx.x;                    // 0..255
    const int lane = tid & 31;
    const int w    = tid >> 5;                       // 0..7

    const float* base_bt = qkv + (size_t)(b * Tt) * QKVN + h * HS;

    // Load K (transposed) and V: thread pair (row = tid>>1) covers one row.
    {
        const int row   = tid >> 1;
        const int dhalf = (tid & 1) * 32;
        const float* krow = base_bt + 256 + (size_t)row * QKVN + dhalf;
        const float* vrow = base_bt + 512 + (size_t)row * QKVN + dhalf;
        #pragma unroll
        for (int d4 = 0; d4 < 8; d4++) {
            int d = dhalf + d4 * 4;
            float4 kv = *(const float4*)(krow + d4 * 4);
            Kst[(d + 0) * 128 + row] = kv.x;
            Kst[(d + 1) * 128 + row] = kv.y;
            Kst[(d + 2) * 128 + row] = kv.z;
            Kst[(d + 3) * 128 + row] = kv.w;
            *(float4*)&Vs[row * 68 + d] = *(const float4*)(vrow + d4 * 4);
        }
    }
    __syncthreads();

    const float scale = 0.0625f;  // 256^-0.5
    float* sw = stg + w * 1024;   // union: q [d][8] then p [kk][8]

    #pragma unroll
    for (int pass = 0; pass < 2; pass++) {
        const int r0 = pass * 64 + w * 8;   // rows r0..r0+7

        // stage q: lane j covers d = j and d = j+32 for all 8 rows
        #pragma unroll
        for (int half = 0; half < 2; half++) {
            int d = lane + half * 32;
            const float* qc = base_bt + (size_t)r0 * QKVN + d;
            float q0 = qc[0*QKVN], q1 = qc[1*QKVN], q2 = qc[2*QKVN], q3 = qc[3*QKVN];
            float q4 = qc[4*QKVN], q5 = qc[5*QKVN], q6 = qc[6*QKVN], q7 = qc[7*QKVN];
            float4 a; a.x = q0; a.y = q1; a.z = q2; a.w = q3;
            float4 c; c.x = q4; c.y = q5; c.z = q6; c.w = q7;
            *(float4*)&sw[d * 8]     = a;
            *(float4*)&sw[d * 8 + 4] = c;
        }
        __syncwarp();

        // scores: s[i][e] for key kk = lane + 32*e
        float s[8][4];
        #pragma unroll
        for (int i = 0; i < 8; i++)
            #pragma unroll
            for (int e = 0; e < 4; e++) s[i][e] = 0.f;

        #pragma unroll 4
        for (int d = 0; d < 64; d++) {
            const float* kd = &Kst[d * 128];
            float k0 = kd[lane], k1 = kd[lane + 32], k2 = kd[lane + 64], k3 = kd[lane + 96];
            float4 qa = *(const float4*)&sw[d * 8];       // rows 0-3 (broadcast)
            float4 qb = *(const float4*)&sw[d * 8 + 4];   // rows 4-7 (broadcast)
            s[0][0] = fmaf(qa.x, k0, s[0][0]); s[0][1] = fmaf(qa.x, k1, s[0][1]);
            s[0][2] = fmaf(qa.x, k2, s[0][2]); s[0][3] = fmaf(qa.x, k3, s[0][3]);
            s[1][0] = fmaf(qa.y, k0, s[1][0]); s[1][1] = fmaf(qa.y, k1, s[1][1]);
            s[1][2] = fmaf(qa.y, k2, s[1][2]); s[1][3] = fmaf(qa.y, k3, s[1][3]);
            s[2][0] = fmaf(qa.z, k0, s[2][0]); s[2][1] = fmaf(qa.z, k1, s[2][1]);
            s[2][2] = fmaf(qa.z, k2, s[2][2]); s[2][3] = fmaf(qa.z, k3, s[2][3]);
            s[3][0] = fmaf(qa.w, k0, s[3][0]); s[3][1] = fmaf(qa.w, k1, s[3][1]);
            s[3][2] = fmaf(qa.w, k2, s[3][2]); s[3][3] = fmaf(qa.w, k3, s[3][3]);
            s[4][0] = fmaf(qb.x, k0, s[4][0]); s[4][1] = fmaf(qb.x, k1, s[4][1]);
            s[4][2] = fmaf(qb.x, k2, s[4][2]); s[4][3] = fmaf(qb.x, k3, s[4][3]);
            s[5][0] = fmaf(qb.y, k0, s[5][0]); s[5][1] = fmaf(qb.y, k1, s[5][1]);
            s[5][2] = fmaf(qb.y, k2, s[5][2]); s[5][3] = fmaf(qb.y, k3, s[5][3]);
            s[6][0] = fmaf(qb.z, k0, s[6][0]); s[6][1] = fmaf(qb.z, k1, s[6][1]);
            s[6][2] = fmaf(qb.z, k2, s[6][2]); s[6][3] = fmaf(qb.z, k3, s[6][3]);
            s[7][0] = fmaf(qb.w, k0, s[7][0]); s[7][1] = fmaf(qb.w, k1, s[7][1]);
            s[7][2] = fmaf(qb.w, k2, s[7][2]); s[7][3] = fmaf(qb.w, k3, s[7][3]);
        }
        __syncwarp();   // q reads done before p overwrites sw

        // softmax per row; stage p into sw[kk*8 + i] (zeros for masked keys)
        #pragma unroll
        for (int i = 0; i < 8; i++) {
            const int qr = r0 + i;
            float e[4];
            float mx = -1e30f;
            #pragma unroll
            for (int ee = 0; ee < 4; ee++) {
                int kk = lane + 32 * ee;
                float sv = s[i][ee] * scale;
                s[i][ee] = sv;
                if (kk <= qr) mx = fmaxf(mx, sv);
            }
            #pragma unroll
            for (int off = 16; off > 0; off >>= 1)
                mx = fmaxf(mx, __shfl_xor_sync(0xffffffffu, mx, off));
            float sum = 0.f;
            #pragma unroll
            for (int ee = 0; ee < 4; ee++) {
                int kk = lane + 32 * ee;
                e[ee] = (kk <= qr) ? __expf(s[i][ee] - mx) : 0.f;
                sum += e[ee];
            }
            #pragma unroll
            for (int off = 16; off > 0; off >>= 1)
                sum += __shfl_xor_sync(0xffffffffu, sum, off);
            float rs = 1.0f / sum;
            #pragma unroll
            for (int ee = 0; ee < 4; ee++) s[i][ee] = e[ee] * rs;  // reuse s as p
        }
        #pragma unroll
        for (int ee = 0; ee < 4; ee++) {
            int kk = lane + 32 * ee;
            float4 pa; pa.x = s[0][ee]; pa.y = s[1][ee]; pa.z = s[2][ee]; pa.w = s[3][ee];
            float4 pb; pb.x = s[4][ee]; pb.y = s[5][ee]; pb.z = s[6][ee]; pb.w = s[7][ee];
            *(float4*)&sw[kk * 8]     = pa;
            *(float4*)&sw[kk * 8 + 4] = pb;
        }
        __syncwarp();

        // PV: lane owns dims d0 = 2*lane, d1 = 2*lane+1
        float o[8][2];
        #pragma unroll
        for (int i = 0; i < 8; i++) { o[i][0] = 0.f; o[i][1] = 0.f; }
        const int kmax = r0 + 7;   // largest row in pass; masked p are 0
        #pragma unroll 2
        for (int kk = 0; kk <= kmax; kk++) {
            float2 v = *(const float2*)&Vs[kk * 68 + 2 * lane];
            float4 pa = *(const float4*)&sw[kk * 8];       // rows 0-3 (broadcast)
            float4 pb = *(const float4*)&sw[kk * 8 + 4];   // rows 4-7 (broadcast)
            o[0][0] = fmaf(pa.x, v.x, o[0][0]); o[0][1] = fmaf(pa.x, v.y, o[0][1]);
            o[1][0] = fmaf(pa.y, v.x, o[1][0]); o[1][1] = fmaf(pa.y, v.y, o[1][1]);
            o[2][0] = fmaf(pa.z, v.x, o[2][0]); o[2][1] = fmaf(pa.z, v.y, o[2][1]);
            o[3][0] = fmaf(pa.w, v.x, o[3][0]); o[3][1] = fmaf(pa.w, v.y, o[3][1]);
            o[4][0] = fmaf(pb.x, v.x, o[4][0]); o[4][1] = fmaf(pb.x, v.y, o[4][1]);
            o[5][0] = fmaf(pb.y, v.x, o[5][0]); o[5][1] = fmaf(pb.y, v.y, o[5][1]);
            o[6][0] = fmaf(pb.z, v.x, o[6][0]); o[6][1] = fmaf(pb.z, v.y, o[6][1]);
            o[7][0] = fmaf(pb.w, v.x, o[7][0]); o[7][1] = fmaf(pb.w, v.y, o[7][1]);
        }

        #pragma unroll
        for (int i = 0; i < 8; i++) {
            size_t obase = (size_t)(b * Tt + r0 + i) * Cc + h * HS + 2 * lane;
            __nv_bfloat16 h0 = __float2bfloat16(o[i][0]);
            __nv_bfloat16 h1 = __float2bfloat16(o[i][1]);
            oh[obase]     = h0;
            oh[obase + 1] = h1;
            ol[obase]     = __float2bfloat16(o[i][0] - __bfloat162float(h0));
            ol[obase + 1] = __float2bfloat16(o[i][1] - __bfloat162float(h1));
        }
        __syncwarp();   // sw reused next pass
    }
}

// ================= launch ===================================================
extern "C" void kernel_launch(void* const* d_in, const int* in_sizes, int n_in,
                              void* d_out, int out_size) {
    const int*   idx   = (const int*)  d_in[0];
    const float* tok   = (const float*)d_in[1];
    const float* pos   = (const float*)d_in[2];
    const float* ln1g  = (const float*)d_in[3];
    const float* ln1b  = (const float*)d_in[4];
    const float* wq    = (const float*)d_in[5];
    const float* wk    = (const float*)d_in[6];
    const float* wv    = (const float*)d_in[7];
    const float* projw = (const float*)d_in[8];
    const float* projb = (const float*)d_in[9];
    const float* ln2g  = (const float*)d_in[10];
    const float* ln2b  = (const float*)d_in[11];
    const float* w1    = (const float*)d_in[12];
    const float* b1    = (const float*)d_in[13];
    const float* w2    = (const float*)d_in[14];
    const float* b2    = (const float*)d_in[15];
    const float* lnfg  = (const float*)d_in[16];
    const float* lnfb  = (const float*)d_in[17];
    const float* lmw   = (const float*)d_in[18];
    const float* lmb   = (const float*)d_in[19];
    float* out = (float*)d_out;

    float *x, *qkv;
    __nv_bfloat16 *hh, *hl, *ah, *al, *fh, *fl;
    __nv_bfloat16 *qkvTh, *qkvTl, *pTh, *pTl;
    __nv_bfloat16 *w1Th, *w1Tl, *w2Th, *w2Tl, *lmTh, *lmTl;
    cudaGetSymbolAddress((void**)&x,   g_x);
    cudaGetSymbolAddress((void**)&qkv, g_qkv);
    cudaGetSymbolAddress((void**)&hh, g_hh);  cudaGetSymbolAddress((void**)&hl, g_hl);
    cudaGetSymbolAddress((void**)&ah, g_ah);  cudaGetSymbolAddress((void**)&al, g_al);
    cudaGetSymbolAddress((void**)&fh, g_fh);  cudaGetSymbolAddress((void**)&fl, g_fl);
    cudaGetSymbolAddress((void**)&qkvTh, g_qkvT_h); cudaGetSymbolAddress((void**)&qkvTl, g_qkvT_l);
    cudaGetSymbolAddress((void**)&pTh,  g_pT_h);    cudaGetSymbolAddress((void**)&pTl,  g_pT_l);
    cudaGetSymbolAddress((void**)&w1Th, g_w1T_h);   cudaGetSymbolAddress((void**)&w1Tl, g_w1T_l);
    cudaGetSymbolAddress((void**)&w2Th, g_w2T_h);   cudaGetSymbolAddress((void**)&w2Tl, g_w2T_l);
    cudaGetSymbolAddress((void**)&lmTh, g_lmT_h);   cudaGetSymbolAddress((void**)&lmTl, g_lmT_l);

    cudaFuncSetAttribute(attn_kernel,
                         cudaFuncAttributeMaxDynamicSharedMemorySize, ATTN_SMEM);
    cudaFuncSetAttribute(tc_gemm<false,false,false,false>,
                         cudaFuncAttributeMaxDynamicSharedMemorySize, GSM_SIZE);
    cudaFuncSetAttribute(tc_gemm<true,false,true,false>,
                         cudaFuncAttributeMaxDynamicSharedMemorySize, GSM_SIZE);
    cudaFuncSetAttribute(tc_gemm<true,true,false,true>,
                         cudaFuncAttributeMaxDynamicSharedMemorySize, GSM_SIZE);
    cudaFuncSetAttribute(tc_gemm<true,false,false,false>,
                         cudaFuncAttributeMaxDynamicSharedMemorySize, GSM_SIZE);

    dim3 tb(32, 8);
    const dim3 gC(Cc / 128,   BT / 128);   // N=256
    const dim3 gQ(QKVN / 128, BT / 128);   // N=768
    const dim3 gF(DFF / 128,  BT / 128);   // N=1024
    const dim3 gV(VPAD / 512, BT / 128);   // LM head: 20 x 128, 4 N-tiles/CTA

    // Launch order: index 3 is the profiled launch -> attn_kernel.
    qkv_transpose<<<dim3(QKVN/32, Cc/32, Ll), tb>>>(wq, wk, wv, qkvTh, qkvTl);      // 0
    embed_ln_kernel<<<BT, 256>>>(idx, tok, pos, ln1g, ln1b, x, hh, hl);             // 1
    tc_gemm<false,false,false,false><<<gQ, 256, GSM_SIZE>>>(                        // 2
        hh, hl, qkvTh, qkvTl, nullptr, nullptr, qkv, nullptr, nullptr,
        QKVN, Cc, 1, QKVN);
    attn_kernel<<<Bb * Hh, 256, ATTN_SMEM>>>(qkv, ah, al);                          // 3 (PROFILED)
    transpose_split_g<<<dim3(Cc/32, Cc/32, Ll), tb>>>(projw, pTh, pTl, Cc, Cc,
                                                      (size_t)Cc*Cc, (size_t)Cc*Cc);
    transpose_split_g<<<dim3(DFF/32, Cc/32, Ll), tb>>>(w1, w1Th, w1Tl, Cc, DFF,
                                                       (size_t)Cc*DFF, (size_t)Cc*DFF);
    transpose_split_g<<<dim3(Cc/32, DFF/32, Ll), tb>>>(w2, w2Th, w2Tl, DFF, Cc,
                                                       (size_t)Cc*DFF, (size_t)Cc*DFF);
    transpose_split_g<<<dim3(VPAD/32, Cc/32, 1), tb>>>(lmw, lmTh, lmTl, Cc, Vv, 0, 0);

    for (int l = 0; l < Ll; l++) {
        size_t oQ = (size_t)l * QKVN * Cc;
        size_t o2 = (size_t)l * Cc * Cc;
        size_t oF = (size_t)l * Cc * DFF;

        if (l > 0) {
            ln_split_kernel<<<BT, 256>>>(x, ln1g + l*Cc, ln1b + l*Cc, hh, hl);
            tc_gemm<false,false,false,false><<<gQ, 256, GSM_SIZE>>>(
                hh, hl, qkvTh + oQ, qkvTl + oQ, nullptr, nullptr, qkv,
                nullptr, nullptr, QKVN, Cc, 1, QKVN);
            attn_kernel<<<Bb * Hh, 256, ATTN_SMEM>>>(qkv, ah, al);
        }

        tc_gemm<true,false,true,false><<<gC, 256, GSM_SIZE>>>(
            ah, al, pTh + o2, pTl + o2, projb + l*Cc, x, x, nullptr, nullptr,
            Cc, Cc, 1, Cc);

        ln_split_kernel<<<BT, 256>>>(x, ln2g + l*Cc, ln2b + l*Cc, hh, hl);

        tc_gemm<true,true,false,true><<<gF, 256, GSM_SIZE>>>(
            hh, hl, w1Th + oF, w1Tl + oF, b1 + l*DFF, nullptr, nullptr, fh, fl,
            DFF, Cc, 1, DFF);

        tc_gemm<true,false,true,false><<<gC, 256, GSM_SIZE>>>(
            fh, fl, w2Th + oF, w2Tl + oF, b2 + l*Cc, x, x, nullptr, nullptr,
            Cc, DFF, 1, Cc);
    }

    ln_split_kernel<<<BT, 256>>>(x, lnfg, lnfb, hh, hl);

    tc_gemm<true,false,false,false><<<gV, 256, GSM_SIZE>>>(
        hh, hl, lmTh, lmTl, lmb, nullptr, out, nullptr, nullptr,
        Vv, Cc, 4, VPAD);
}

// round 14
// speedup vs baseline: 1.0598x; 1.0066x over previous
#include <cuda_runtime.h>
#include <cuda_bf16.h>
#include <math.h>
#include <cstdint>

// tcgen05 is only legal on arch-specific targets (sm_103a / sm_100a).
// The harness's nvcc also runs a generic compute_103 PTX pass; guard so that
// pass compiles empty bodies (the sm_103a cubin is what actually runs).
#if !defined(__CUDA_ARCH__) || defined(__CUDA_ARCH_FEAT_SM103_ALL) || \
    defined(__CUDA_ARCH_FEAT_SM100_ALL) || defined(__CUDA_ARCH_FEAT_SM101_ALL)
#define HAS_TCGEN05 1
#else
#define HAS_TCGEN05 0
#endif

// Problem dims
#define Bb   128
#define Tt   128
#define Cc   256
#define Hh   4
#define HS   64
#define Ll   6
#define DFF  1024
#define Vv   10000
#define BT   (Bb*Tt)   // 16384
#define VPAD 10240     // 80*128 (LM head padded to 4-tile groups)
#define QKVN 768

// ================= PTX helpers (sm_103a tcgen05) ===========================
__device__ __forceinline__ uint32_t smem_to_u32(const void* p) {
    uint32_t a;
    asm("{ .reg .u64 t; cvta.to.shared.u64 t, %1; cvt.u32.u64 %0, t; }"
        : "=r"(a) : "l"(p));
    return a;
}

#if HAS_TCGEN05
__device__ __forceinline__ uint32_t elect_one_pred() {
    uint32_t pred;
    asm volatile(
        "{\n\t.reg .pred p;\n\telect.sync _|p, 0xFFFFFFFF;\n\t"
        "selp.b32 %0, 1, 0, p;\n\t}"
        : "=r"(pred));
    return pred;
}
#define TCGEN05_ALLOC(smem_addr, nCols) \
    asm volatile("tcgen05.alloc.cta_group::1.sync.aligned.shared::cta.b32 [%0], %1;" \
        :: "r"((uint32_t)(smem_addr)), "r"((uint32_t)(nCols)) : "memory")
#define TCGEN05_DEALLOC(tmem_addr, nCols) \
    asm volatile("tcgen05.dealloc.cta_group::1.sync.aligned.b32 %0, %1;" \
        :: "r"(tmem_addr), "r"((uint32_t)(nCols)))
#define TCGEN05_RELINQ() \
    asm volatile("tcgen05.relinquish_alloc_permit.cta_group::1.sync.aligned;")
#define TCGEN05_COMMIT(mbar) \
    asm volatile("tcgen05.commit.cta_group::1.mbarrier::arrive::one.shared::cluster.b64 [%0];" \
        :: "r"((uint32_t)(mbar)) : "memory")
#define TCGEN05_FENCE_BEFORE() \
    asm volatile("tcgen05.fence::before_thread_sync;" ::: "memory")
#define TCGEN05_FENCE_AFTER() \
    asm volatile("tcgen05.fence::after_thread_sync;" ::: "memory")
#define TCGEN05_WAIT_LD() \
    asm volatile("tcgen05.wait::ld.sync.aligned;" ::: "memory")
#define FENCE_PROXY_ASYNC_SHARED_CTA() \
    asm volatile("fence.proxy.async.shared::cta;" ::: "memory")
#define MBARRIER_INIT(mbar, count) \
    asm volatile("mbarrier.init.shared.b64 [%0], %1;" \
        :: "r"((uint32_t)(mbar)), "r"((uint32_t)(count)) : "memory")
#define MBARRIER_INVAL(mbar) \
    asm volatile("mbarrier.inval.shared.b64 [%0];" :: "r"((uint32_t)(mbar)) : "memory")
// Non-blocking poll: mbarrier.test_wait in a spin loop, no sleep.
#define MBARRIER_POLL(mbar, parity) do { \
    uint32_t _mbar = (uint32_t)(mbar); \
    uint32_t _par  = (uint32_t)(parity); \
    uint32_t _done = 0; \
    while (!_done) { \
        asm volatile( \
            "{\n\t.reg .pred p;\n\t" \
            "mbarrier.test_wait.parity.acquire.cta.shared::cta.b64 p, [%1], %2;\n\t" \
            "selp.b32 %0, 1, 0, p;\n\t}" \
            : "=r"(_done) : "r"(_mbar), "r"(_par) : "memory"); \
    } \
} while (0)
// Async 16B copy global->shared (LDGSTS). Register-free, deep MLP.
__device__ __forceinline__ void cp_async16(uint32_t dst, const void* src) {
    asm volatile("cp.async.cg.shared.global [%0], [%1], 16;"
        :: "r"(dst), "l"(src) : "memory");
}
#define CP_ASYNC_COMMIT() asm volatile("cp.async.commit_group;" ::: "memory")
#define CP_ASYNC_WAIT0()  asm volatile("cp.async.wait_group 0;" ::: "memory")
#define TCGEN05_LD_32X32B_X32(r, tmem_addr) \
    asm volatile( \
        "tcgen05.ld.sync.aligned.32x32b.x32.b32 " \
        "{%0, %1, %2, %3, %4, %5, %6, %7, " \
        " %8, %9, %10, %11, %12, %13, %14, %15, " \
        " %16, %17, %18, %19, %20, %21, %22, %23, " \
        " %24, %25, %26, %27, %28, %29, %30, %31}, [%32];" \
        : "=r"((r)[0]),  "=r"((r)[1]),  "=r"((r)[2]),  "=r"((r)[3]), \
          "=r"((r)[4]),  "=r"((r)[5]),  "=r"((r)[6]),  "=r"((r)[7]), \
          "=r"((r)[8]),  "=r"((r)[9]),  "=r"((r)[10]), "=r"((r)[11]), \
          "=r"((r)[12]), "=r"((r)[13]), "=r"((r)[14]), "=r"((r)[15]), \
          "=r"((r)[16]), "=r"((r)[17]), "=r"((r)[18]), "=r"((r)[19]), \
          "=r"((r)[20]), "=r"((r)[21]), "=r"((r)[22]), "=r"((r)[23]), \
          "=r"((r)[24]), "=r"((r)[25]), "=r"((r)[26]), "=r"((r)[27]), \
          "=r"((r)[28]), "=r"((r)[29]), "=r"((r)[30]), "=r"((r)[31]) \
        : "r"(tmem_addr))

// cg1 bf16 SS MMA (A in SMEM, B in SMEM), fp32 accumulate
__device__ __forceinline__ void mma_bf16_ss(uint32_t d, uint64_t a, uint64_t b,
                                            uint32_t idesc, bool en) {
    uint32_t e = en ? 1u : 0u;
    asm volatile(
        "{\n\t.reg .pred p;\n\t"
        "setp.ne.u32 p, %5, 0;\n\t"
        "tcgen05.mma.cta_group::1.kind::f16 [%0], %1, %2, %3, {%4, %4, %4, %4}, p;\n\t}"
        :: "r"(d), "l"(a), "l"(b), "r"(idesc), "r"(0u), "r"(e)
        : "memory");
}
#endif  // HAS_TCGEN05

// 64-bit SMEM descriptor: SW128, Blackwell v1, LBO=1, SBO=64 (K-major 128B rows)
static __device__ __forceinline__ uint64_t make_desc_sw128(uint32_t addr) {
    const uint64_t base =
        (uint64_t(2)  << 61) | (uint64_t(1) << 46) |
        (uint64_t(64) << 32) | (uint64_t(1) << 16);
    return base | ((uint64_t)(addr >> 4) & 0x3FFF);
}
#define SW128(bo) ((bo) ^ (((bo) >> 3) & 0x70))

// ================= scratch (device globals) ================================
__device__ __align__(16) float g_x  [BT*Cc];
__device__ __align__(16) float g_qkv[BT*QKVN];
// bf16 hi/lo activations
__device__ __align__(16) __nv_bfloat16 g_hh[BT*Cc],  g_hl[BT*Cc];
__device__ __align__(16) __nv_bfloat16 g_ah[BT*Cc],  g_al[BT*Cc];
__device__ __align__(16) __nv_bfloat16 g_fh[BT*DFF], g_fl[BT*DFF];
// transposed+split weights: [N(pad), K] K-major
__device__ __align__(16) __nv_bfloat16 g_qkvT_h[Ll*QKVN*Cc], g_qkvT_l[Ll*QKVN*Cc];
__device__ __align__(16) __nv_bfloat16 g_pT_h [Ll*Cc*Cc],    g_pT_l [Ll*Cc*Cc];
__device__ __align__(16) __nv_bfloat16 g_w1T_h[Ll*DFF*Cc],   g_w1T_l[Ll*DFF*Cc];
__device__ __align__(16) __nv_bfloat16 g_w2T_h[Ll*Cc*DFF],   g_w2T_l[Ll*Cc*DFF];
__device__ __align__(16) __nv_bfloat16 g_lmT_h[VPAD*Cc],     g_lmT_l[VPAD*Cc];

// ================= small kernels ===========================================
// Fused embedding + LN1(layer 0): one block per row. Writes x AND hh/hl.
__global__ void embed_ln_kernel(const int* __restrict__ idx,
                                const float* __restrict__ tok,
                                const float* __restrict__ pos,
                                const float* __restrict__ g,
                                const float* __restrict__ b,
                                float* __restrict__ x,
                                __nv_bfloat16* __restrict__ oh,
                                __nv_bfloat16* __restrict__ ol) {
    int row = blockIdx.x;
    int tid = threadIdx.x;
    int t   = row & (Tt - 1);
    float v = tok[idx[row] * Cc + tid] + pos[t * Cc + tid];
    x[row * Cc + tid] = v;
    float s = v, s2 = v * v;
    #pragma unroll
    for (int off = 16; off > 0; off >>= 1) {
        s  += __shfl_xor_sync(0xffffffffu, s,  off);
        s2 += __shfl_xor_sync(0xffffffffu, s2, off);
    }
    __shared__ float ss[8], ss2[8];
    __shared__ float mean_s, rstd_s;
    int w = tid >> 5, l = tid & 31;
    if (l == 0) { ss[w] = s; ss2[w] = s2; }
    __syncthreads();
    if (tid == 0) {
        float S = 0.f, S2 = 0.f;
        #pragma unroll
        for (int i = 0; i < 8; i++) { S += ss[i]; S2 += ss2[i]; }
        float m   = S * (1.0f / Cc);
        float var = S2 * (1.0f / Cc) - m * m;
        mean_s = m;
        rstd_s = rsqrtf(var + 1e-5f);
    }
    __syncthreads();
    float y = (v - mean_s) * rstd_s * g[tid] + b[tid];
    __nv_bfloat16 hi = __float2bfloat16(y);
    oh[row * Cc + tid] = hi;
    ol[row * Cc + tid] = __float2bfloat16(y - __bfloat162float(hi));
}

// generic: W [K,N] fp32 (layer-strided) -> out [Npad,K] bf16 hi/lo
__global__ void transpose_split_g(const float* __restrict__ W,
                                  __nv_bfloat16* __restrict__ oh,
                                  __nv_bfloat16* __restrict__ ol,
                                  int K, int N,
                                  size_t wstride, size_t ostride) {
    __shared__ float t[32][33];
    int l  = blockIdx.z;
    W  += (size_t)l * wstride;
    oh += (size_t)l * ostride;
    ol += (size_t)l * ostride;
    int n0 = blockIdx.x * 32, k0 = blockIdx.y * 32;
    int tx = threadIdx.x, ty = threadIdx.y;
    #pragma unroll
    for (int i = 0; i < 4; i++) {
        int k = k0 + ty + i * 8;
        int n = n0 + tx;
        t[ty + i * 8][tx] = (n < N) ? W[(size_t)k * N + n] : 0.f;
    }
    __syncthreads();
    #pragma unroll
    for (int i = 0; i < 4; i++) {
        int n = n0 + ty + i * 8;
        int k = k0 + tx;
        float v = t[tx][ty + i * 8];
        __nv_bfloat16 hi = __float2bfloat16(v);
        oh[(size_t)n * K + k] = hi;
        ol[(size_t)n * K + k] = __float2bfloat16(v - __bfloat162float(hi));
    }
}

// fused QKV transpose: wq/wk/wv [L][256][256] -> out [L][768][256]
__global__ void qkv_transpose(const float* __restrict__ wq,
                              const float* __restrict__ wk,
                              const float* __restrict__ wv,
                              __nv_bfloat16* __restrict__ oh,
                              __nv_bfloat16* __restrict__ ol) {
    __shared__ float t[32][33];
    int l  = blockIdx.z;
    int n0 = blockIdx.x * 32, k0 = blockIdx.y * 32;
    const float* W;
    int nb;
    if      (n0 < 256) { W = wq + (size_t)l * Cc * Cc; nb = n0; }
    else if (n0 < 512) { W = wk + (size_t)l * Cc * Cc; nb = n0 - 256; }
    else               { W = wv + (size_t)l * Cc * Cc; nb = n0 - 512; }
    oh += (size_t)l * QKVN * Cc;
    ol += (size_t)l * QKVN * Cc;
    int tx = threadIdx.x, ty = threadIdx.y;
    #pragma unroll
    for (int i = 0; i < 4; i++) {
        int k = k0 + ty + i * 8;
        t[ty + i * 8][tx] = W[(size_t)k * Cc + nb + tx];
    }
    __syncthreads();
    #pragma unroll
    for (int i = 0; i < 4; i++) {
        int n = n0 + ty + i * 8;
        int k = k0 + tx;
        float v = t[tx][ty + i * 8];
        __nv_bfloat16 hi = __float2bfloat16(v);
        oh[(size_t)n * Cc + k] = hi;
        ol[(size_t)n * Cc + k] = __float2bfloat16(v - __bfloat162float(hi));
    }
}

// LayerNorm, outputs bf16 hi/lo split
__global__ void ln_split_kernel(const float* __restrict__ x,
                                const float* __restrict__ g,
                                const float* __restrict__ b,
                                __nv_bfloat16* __restrict__ oh,
                                __nv_bfloat16* __restrict__ ol) {
    int row = blockIdx.x;
    int tid = threadIdx.x;
    float v = x[row * Cc + tid];
    float s = v, s2 = v * v;
    #pragma unroll
    for (int off = 16; off > 0; off >>= 1) {
        s  += __shfl_xor_sync(0xffffffffu, s,  off);
        s2 += __shfl_xor_sync(0xffffffffu, s2, off);
    }
    __shared__ float ss[8], ss2[8];
    __shared__ float mean_s, rstd_s;
    int w = tid >> 5, l = tid & 31;
    if (l == 0) { ss[w] = s; ss2[w] = s2; }
    __syncthreads();
    if (tid == 0) {
        float S = 0.f, S2 = 0.f;
        #pragma unroll
        for (int i = 0; i < 8; i++) { S += ss[i]; S2 += ss2[i]; }
        float m   = S * (1.0f / Cc);
        float var = S2 * (1.0f / Cc) - m * m;
        mean_s = m;
        rstd_s = rsqrtf(var + 1e-5f);
    }
    __syncthreads();
    float y = (v - mean_s) * rstd_s * g[tid] + b[tid];
    __nv_bfloat16 hi = __float2bfloat16(y);
    oh[row * Cc + tid] = hi;
    ol[row * Cc + tid] = __float2bfloat16(y - __bfloat162float(hi));
}

// ================= tcgen05 GEMM (cp.async loads, coalesced epilogue) ========
// Identical to R8-R13 (the winners) — protect the win.
#define GSM_TPTR 0
#define GSM_MBAR 8
#define GSM_AH   1024
#define GSM_AL   (1024 + 16384)
#define GSM_BH   (1024 + 32768)
#define GSM_BL   (1024 + 49152)
#define EPI_PAD  132                       // fp32 row pitch (16B-aligned rows)
#define GSM_SIZE (1024 + 128*EPI_PAD*4)    // 68608 >= 1024+65536 operand area
#define GEMM_IDESC 0x8200490u   // f32 acc, bf16 a/b, N=128, M=128

template<bool BIAS, bool RELU, bool RESID, bool SPLIT>
__global__ __launch_bounds__(256)
void tc_gemm(const __nv_bfloat16* __restrict__ Ah, const __nv_bfloat16* __restrict__ Al,
             const __nv_bfloat16* __restrict__ Bh, const __nv_bfloat16* __restrict__ Bl,
             const float* __restrict__ bias, const float* __restrict__ res,
             float* __restrict__ outf,
             __nv_bfloat16* __restrict__ oh, __nv_bfloat16* __restrict__ ol,
             int Nstore, int K, int ntiles, int Npad) {
#if HAS_TCGEN05
    extern __shared__ char smem[];
    const uint32_t smem_base = smem_to_u32(smem);
    const int tid  = threadIdx.x;
    const int wid  = tid >> 5;
    const int lane = tid & 31;
    const int bm   = blockIdx.y * 128;
    const int bn0  = blockIdx.x * 128 * ntiles;

    if (wid == 0) {
        TCGEN05_ALLOC(smem_base + GSM_TPTR, 128);
        TCGEN05_RELINQ();
    }
    if (tid == 0) MBARRIER_INIT(smem_base + GSM_MBAR, 1);
    __syncthreads();
    uint32_t tmem;
    asm volatile("ld.shared.b32 %0, [%1];" : "=r"(tmem) : "r"(smem_base + GSM_TPTR));

    const uint64_t dAh = make_desc_sw128(smem_base + GSM_AH);
    const uint64_t dAl = make_desc_sw128(smem_base + GSM_AL);
    const uint64_t dBh = make_desc_sw128(smem_base + GSM_BH);
    const uint64_t dBl = make_desc_sw128(smem_base + GSM_BL);

    // per-thread load mapping: 4 iters x one 16B vector per tile buffer
    const int lr = tid >> 3;            // row base 0..31 (+32*i)
    const int lb = (tid & 7) * 16;      // byte offset in 128B row

    const int nchunks = K >> 6;   // K/64
    int cc = 0;                   // global chunk counter (mbarrier parity)

    for (int t = 0; t < ntiles; t++) {
        const int bn = bn0 + t * 128;
        if (bn >= Npad) break;

        for (int c = 0; c < nchunks; c++) {
            const int k0 = c << 6;
            #pragma unroll
            for (int i = 0; i < 4; i++) {
                int r = lr + i * 32;
                uint32_t so = SW128(r * 128 + lb);
                const char* sa = (const char*)(Ah + (size_t)(bm + r) * K + k0) + lb;
                const char* sb = (const char*)(Al + (size_t)(bm + r) * K + k0) + lb;
                const char* sc = (const char*)(Bh + (size_t)(bn + r) * K + k0) + lb;
                const char* sd = (const char*)(Bl + (size_t)(bn + r) * K + k0) + lb;
                cp_async16(smem_base + GSM_AH + so, sa);
                cp_async16(smem_base + GSM_AL + so, sb);
                cp_async16(smem_base + GSM_BH + so, sc);
                cp_async16(smem_base + GSM_BL + so, sd);
            }
            CP_ASYNC_COMMIT();
            CP_ASYNC_WAIT0();
            FENCE_PROXY_ASYNC_SHARED_CTA();
            __syncthreads();

            if (wid == 0 && elect_one_pred()) {
                #pragma unroll
                for (int ks = 0; ks < 4; ks++) {
                    uint64_t oa = (uint64_t)(ks * 2);
                    mma_bf16_ss(tmem, dAh + oa, dBh + oa, GEMM_IDESC, !(c == 0 && ks == 0));
                    mma_bf16_ss(tmem, dAh + oa, dBl + oa, GEMM_IDESC, true);
                    mma_bf16_ss(tmem, dAl + oa, dBh + oa, GEMM_IDESC, true);
                }
                TCGEN05_COMMIT(smem_base + GSM_MBAR);
            }
            // warp 0 polls (no sleep), everyone else joins at the barrier
            if (wid == 0) MBARRIER_POLL(smem_base + GSM_MBAR, cc & 1);
            __syncthreads();
            cc++;
        }
        TCGEN05_FENCE_AFTER();

        // ---- epilogue: transpose through smem, fully coalesced stores ----
        {
            float* eps = (float*)(smem + GSM_AH);   // reuse operand smem
            const int wp   = wid & 3;
            const int colg = (wid >> 2) * 64;
            const int ml   = wp * 32 + lane;        // local row (m)
            #pragma unroll
            for (int half = 0; half < 2; half++) {
                int cb = colg + half * 32;
                uint32_t r[32];
                TCGEN05_LD_32X32B_X32(r, tmem + cb);
                TCGEN05_WAIT_LD();
                #pragma unroll
                for (int j = 0; j < 32; j++)
                    eps[ml * EPI_PAD + cb + j] = __uint_as_float(r[j]);
            }
            TCGEN05_FENCE_BEFORE();
            __syncthreads();

            // 128 rows x 32 float4-cols = 4096 quads; 256 threads x 16 iters.
            #pragma unroll 4
            for (int it = 0; it < 16; it++) {
                int q   = it * 256 + tid;
                int row = q >> 5;
                int c4  = (q & 31) << 2;
                int n   = bn + c4;
                if (n < Nstore) {
                    float4 v = *(const float4*)&eps[row * EPI_PAD + c4];
                    float vals[4] = {v.x, v.y, v.z, v.w};
                    size_t base = (size_t)(bm + row) * Nstore + n;
                    #pragma unroll
                    for (int e = 0; e < 4; e++) {
                        if (BIAS) vals[e] += bias[n + e];
                        if (RELU) vals[e] = fmaxf(vals[e], 0.f);
                    }
                    if (SPLIT) {
                        #pragma unroll
                        for (int e = 0; e < 4; e++) {
                            __nv_bfloat16 hi = __float2bfloat16(vals[e]);
                            oh[base + e] = hi;
                            ol[base + e] = __float2bfloat16(vals[e] - __bfloat162float(hi));
                        }
                    } else {
                        if (RESID) {
                            float4 rv = *(const float4*)&res[base];
                            vals[0] += rv.x; vals[1] += rv.y;
                            vals[2] += rv.z; vals[3] += rv.w;
                        }
                        float4 o;
                        o.x = vals[0]; o.y = vals[1]; o.z = vals[2]; o.w = vals[3];
                        *(float4*)&outf[base] = o;
                    }
                }
            }
            __syncthreads();   // eps dead before next tile's operand loads
        }
    }

    if (tid == 0) MBARRIER_INVAL(smem_base + GSM_MBAR);
    __syncthreads();
    if (wid == 0) TCGEN05_DEALLOC(tmem, 128);
#endif  // HAS_TCGEN05
}

// ================= fused causal attention (8-row passes, mask-skipped QK) ===
// smem: Kst[64][128] (32KB) + Vs[128][68] (34KB) + stg[8][1024] (32KB) = 98KB
// Each warp runs 2 passes of 8 consecutive rows. QK now only processes the
// key-groups the causal mask allows: ng = (kmax>>5)+1 of 4 (warp-uniform),
// eliminating ~37% of QK LDS+FMA work. Skipped groups were p=0 anyway.
#define ATTN_SMEM ((64*128 + 128*68 + 8*1024) * 4)   // 100352 B

template<int NG>
__device__ __forceinline__ void qk_groups(const float* __restrict__ Kst,
                                          const float* __restrict__ sw,
                                          int lane, float s[8][4]) {
    #pragma unroll 4
    for (int d = 0; d < 64; d++) {
        const float* kd = &Kst[d * 128];
        float k[NG];
        #pragma unroll
        for (int e = 0; e < NG; e++) k[e] = kd[lane + 32 * e];
        float4 qa = *(const float4*)&sw[d * 8];       // rows 0-3 (broadcast)
        float4 qb = *(const float4*)&sw[d * 8 + 4];   // rows 4-7 (broadcast)
        float qv[8] = {qa.x, qa.y, qa.z, qa.w, qb.x, qb.y, qb.z, qb.w};
        #pragma unroll
        for (int i = 0; i < 8; i++)
            #pragma unroll
            for (int e = 0; e < NG; e++)
                s[i][e] = fmaf(qv[i], k[e], s[i][e]);
    }
}

__global__ __launch_bounds__(256)
void attn_kernel(const float* __restrict__ qkv,
                 __nv_bfloat16* __restrict__ oh, __nv_bfloat16* __restrict__ ol) {
    extern __shared__ float sm[];
    float* Kst = sm;                                 // [64][128] d-major
    float* Vs  = sm + 64 * 128;                      // [128][68]
    float* stg = sm + 64 * 128 + 128 * 68;           // [8][1024] union q/p

    const int b    = blockIdx.x >> 2;
    const int h    = blockIdx.x & 3;
    const int tid  = threadIdx.x;                    // 0..255
    const int lane = tid & 31;
    const int w    = tid >> 5;                       // 0..7

    const float* base_bt = qkv + (size_t)(b * Tt) * QKVN + h * HS;

    // Load K (transposed) and V: thread pair (row = tid>>1) covers one row.
    {
        const int row   = tid >> 1;
        const int dhalf = (tid & 1) * 32;
        const float* krow = base_bt + 256 + (size_t)row * QKVN + dhalf;
        const float* vrow = base_bt + 512 + (size_t)row * QKVN + dhalf;
        #pragma unroll
        for (int d4 = 0; d4 < 8; d4++) {
            int d = dhalf + d4 * 4;
            float4 kv = *(const float4*)(krow + d4 * 4);
            Kst[(d + 0) * 128 + row] = kv.x;
            Kst[(d + 1) * 128 + row] = kv.y;
            Kst[(d + 2) * 128 + row] = kv.z;
            Kst[(d + 3) * 128 + row] = kv.w;
            *(float4*)&Vs[row * 68 + d] = *(const float4*)(vrow + d4 * 4);
        }
    }
    __syncthreads();

    const float scale = 0.0625f;  // 256^-0.5
    float* sw = stg + w * 1024;   // union: q [d][8] then p [kk][8]

    #pragma unroll
    for (int pass = 0; pass < 2; pass++) {
        const int r0   = pass * 64 + w * 8;   // rows r0..r0+7
        const int kmax = r0 + 7;
        const int ng   = (kmax >> 5) + 1;     // live key groups (warp-uniform)

        // stage q: lane j covers d = j and d = j+32 for all 8 rows
        #pragma unroll
        for (int half = 0; half < 2; half++) {
            int d = lane + half * 32;
            const float* qc = base_bt + (size_t)r0 * QKVN + d;
            float q0 = qc[0*QKVN], q1 = qc[1*QKVN], q2 = qc[2*QKVN], q3 = qc[3*QKVN];
            float q4 = qc[4*QKVN], q5 = qc[5*QKVN], q6 = qc[6*QKVN], q7 = qc[7*QKVN];
            float4 a; a.x = q0; a.y = q1; a.z = q2; a.w = q3;
            float4 c; c.x = q4; c.y = q5; c.z = q6; c.w = q7;
            *(float4*)&sw[d * 8]     = a;
            *(float4*)&sw[d * 8 + 4] = c;
        }
        __syncwarp();

        // scores: s[i][e] for key kk = lane + 32*e (only e < ng computed)
        float s[8][4];
        #pragma unroll
        for (int i = 0; i < 8; i++)
            #pragma unroll
            for (int e = 0; e < 4; e++) s[i][e] = 0.f;

        if      (ng == 1) qk_groups<1>(Kst, sw, lane, s);
        else if (ng == 2) qk_groups<2>(Kst, sw, lane, s);
        else if (ng == 3) qk_groups<3>(Kst, sw, lane, s);
        else              qk_groups<4>(Kst, sw, lane, s);
        __syncwarp();   // q reads done before p overwrites sw

        // softmax per row (e >= ng stays masked: kk = lane+32e > kmax >= qr)
        #pragma unroll
        for (int i = 0; i < 8; i++) {
            const int qr = r0 + i;
            float e[4];
            float mx = -1e30f;
            #pragma unroll
            for (int ee = 0; ee < 4; ee++) {
                int kk = lane + 32 * ee;
                float sv = s[i][ee] * scale;
                s[i][ee] = sv;
                if (kk <= qr) mx = fmaxf(mx, sv);
            }
            #pragma unroll
            for (int off = 16; off > 0; off >>= 1)
                mx = fmaxf(mx, __shfl_xor_sync(0xffffffffu, mx, off));
            float sum = 0.f;
            #pragma unroll
            for (int ee = 0; ee < 4; ee++) {
                int kk = lane + 32 * ee;
                e[ee] = (kk <= qr) ? __expf(s[i][ee] - mx) : 0.f;
                sum += e[ee];
            }
            #pragma unroll
            for (int off = 16; off > 0; off >>= 1)
                sum += __shfl_xor_sync(0xffffffffu, sum, off);
            float rs = 1.0f / sum;
            #pragma unroll
            for (int ee = 0; ee < 4; ee++) s[i][ee] = e[ee] * rs;  // reuse s as p
        }
        // stage p only for live groups (PV never reads kk > kmax)
        for (int ee = 0; ee < ng; ee++) {
            int kk = lane + 32 * ee;
            float4 pa; pa.x = s[0][ee]; pa.y = s[1][ee]; pa.z = s[2][ee]; pa.w = s[3][ee];
            float4 pb; pb.x = s[4][ee]; pb.y = s[5][ee]; pb.z = s[6][ee]; pb.w = s[7][ee];
            *(float4*)&sw[kk * 8]     = pa;
            *(float4*)&sw[kk * 8 + 4] = pb;
        }
        __syncwarp();

        // PV: lane owns dims d0 = 2*lane, d1 = 2*lane+1
        float o[8][2];
        #pragma unroll
        for (int i = 0; i < 8; i++) { o[i][0] = 0.f; o[i][1] = 0.f; }
        #pragma unroll 2
        for (int kk = 0; kk <= kmax; kk++) {
            float2 v = *(const float2*)&Vs[kk * 68 + 2 * lane];
            float4 pa = *(const float4*)&sw[kk * 8];       // rows 0-3 (broadcast)
            float4 pb = *(const float4*)&sw[kk * 8 + 4];   // rows 4-7 (broadcast)
            o[0][0] = fmaf(pa.x, v.x, o[0][0]); o[0][1] = fmaf(pa.x, v.y, o[0][1]);
            o[1][0] = fmaf(pa.y, v.x, o[1][0]); o[1][1] = fmaf(pa.y, v.y, o[1][1]);
            o[2][0] = fmaf(pa.z, v.x, o[2][0]); o[2][1] = fmaf(pa.z, v.y, o[2][1]);
            o[3][0] = fmaf(pa.w, v.x, o[3][0]); o[3][1] = fmaf(pa.w, v.y, o[3][1]);
            o[4][0] = fmaf(pb.x, v.x, o[4][0]); o[4][1] = fmaf(pb.x, v.y, o[4][1]);
            o[5][0] = fmaf(pb.y, v.x, o[5][0]); o[5][1] = fmaf(pb.y, v.y, o[5][1]);
            o[6][0] = fmaf(pb.z, v.x, o[6][0]); o[6][1] = fmaf(pb.z, v.y, o[6][1]);
            o[7][0] = fmaf(pb.w, v.x, o[7][0]); o[7][1] = fmaf(pb.w, v.y, o[7][1]);
        }

        #pragma unroll
        for (int i = 0; i < 8; i++) {
            size_t obase = (size_t)(b * Tt + r0 + i) * Cc + h * HS + 2 * lane;
            __nv_bfloat16 h0 = __float2bfloat16(o[i][0]);
            __nv_bfloat16 h1 = __float2bfloat16(o[i][1]);
            oh[obase]     = h0;
            oh[obase + 1] = h1;
            ol[obase]     = __float2bfloat16(o[i][0] - __bfloat162float(h0));
            ol[obase + 1] = __float2bfloat16(o[i][1] - __bfloat162float(h1));
        }
        __syncwarp();   // sw reused next pass
    }
}

// ================= launch ===================================================
extern "C" void kernel_launch(void* const* d_in, const int* in_sizes, int n_in,
                              void* d_out, int out_size) {
    const int*   idx   = (const int*)  d_in[0];
    const float* tok   = (const float*)d_in[1];
    const float* pos   = (const float*)d_in[2];
    const float* ln1g  = (const float*)d_in[3];
    const float* ln1b  = (const float*)d_in[4];
    const float* wq    = (const float*)d_in[5];
    const float* wk    = (const float*)d_in[6];
    const float* wv    = (const float*)d_in[7];
    const float* projw = (const float*)d_in[8];
    const float* projb = (const float*)d_in[9];
    const float* ln2g  = (const float*)d_in[10];
    const float* ln2b  = (const float*)d_in[11];
    const float* w1    = (const float*)d_in[12];
    const float* b1    = (const float*)d_in[13];
    const float* w2    = (const float*)d_in[14];
    const float* b2    = (const float*)d_in[15];
    const float* lnfg  = (const float*)d_in[16];
    const float* lnfb  = (const float*)d_in[17];
    const float* lmw   = (const float*)d_in[18];
    const float* lmb   = (const float*)d_in[19];
    float* out = (float*)d_out;

    float *x, *qkv;
    __nv_bfloat16 *hh, *hl, *ah, *al, *fh, *fl;
    __nv_bfloat16 *qkvTh, *qkvTl, *pTh, *pTl;
    __nv_bfloat16 *w1Th, *w1Tl, *w2Th, *w2Tl, *lmTh, *lmTl;
    cudaGetSymbolAddress((void**)&x,   g_x);
    cudaGetSymbolAddress((void**)&qkv, g_qkv);
    cudaGetSymbolAddress((void**)&hh, g_hh);  cudaGetSymbolAddress((void**)&hl, g_hl);
    cudaGetSymbolAddress((void**)&ah, g_ah);  cudaGetSymbolAddress((void**)&al, g_al);
    cudaGetSymbolAddress((void**)&fh, g_fh);  cudaGetSymbolAddress((void**)&fl, g_fl);
    cudaGetSymbolAddress((void**)&qkvTh, g_qkvT_h); cudaGetSymbolAddress((void**)&qkvTl, g_qkvT_l);
    cudaGetSymbolAddress((void**)&pTh,  g_pT_h);    cudaGetSymbolAddress((void**)&pTl,  g_pT_l);
    cudaGetSymbolAddress((void**)&w1Th, g_w1T_h);   cudaGetSymbolAddress((void**)&w1Tl, g_w1T_l);
    cudaGetSymbolAddress((void**)&w2Th, g_w2T_h);   cudaGetSymbolAddress((void**)&w2Tl, g_w2T_l);
    cudaGetSymbolAddress((void**)&lmTh, g_lmT_h);   cudaGetSymbolAddress((void**)&lmTl, g_lmT_l);

    cudaFuncSetAttribute(attn_kernel,
                         cudaFuncAttributeMaxDynamicSharedMemorySize, ATTN_SMEM);
    cudaFuncSetAttribute(tc_gemm<false,false,false,false>,
                         cudaFuncAttributeMaxDynamicSharedMemorySize, GSM_SIZE);
    cudaFuncSetAttribute(tc_gemm<true,false,true,false>,
                         cudaFuncAttributeMaxDynamicSharedMemorySize, GSM_SIZE);
    cudaFuncSetAttribute(tc_gemm<true,true,false,true>,
                         cudaFuncAttributeMaxDynamicSharedMemorySize, GSM_SIZE);
    cudaFuncSetAttribute(tc_gemm<true,false,false,false>,
                         cudaFuncAttributeMaxDynamicSharedMemorySize, GSM_SIZE);

    dim3 tb(32, 8);
    const dim3 gC(Cc / 128,   BT / 128);   // N=256
    const dim3 gQ(QKVN / 128, BT / 128);   // N=768
    const dim3 gF(DFF / 128,  BT / 128);   // N=1024
    const dim3 gV(VPAD / 512, BT / 128);   // LM head: 20 x 128, 4 N-tiles/CTA

    // Launch order: index 3 is the profiled launch -> attn_kernel.
    qkv_transpose<<<dim3(QKVN/32, Cc/32, Ll), tb>>>(wq, wk, wv, qkvTh, qkvTl);      // 0
    embed_ln_kernel<<<BT, 256>>>(idx, tok, pos, ln1g, ln1b, x, hh, hl);             // 1
    tc_gemm<false,false,false,false><<<gQ, 256, GSM_SIZE>>>(                        // 2
        hh, hl, qkvTh, qkvTl, nullptr, nullptr, qkv, nullptr, nullptr,
        QKVN, Cc, 1, QKVN);
    attn_kernel<<<Bb * Hh, 256, ATTN_SMEM>>>(qkv, ah, al);                          // 3 (PROFILED)
    transpose_split_g<<<dim3(Cc/32, Cc/32, Ll), tb>>>(projw, pTh, pTl, Cc, Cc,
                                                      (size_t)Cc*Cc, (size_t)Cc*Cc);
    transpose_split_g<<<dim3(DFF/32, Cc/32, Ll), tb>>>(w1, w1Th, w1Tl, Cc, DFF,
                                                       (size_t)Cc*DFF, (size_t)Cc*DFF);
    transpose_split_g<<<dim3(Cc/32, DFF/32, Ll), tb>>>(w2, w2Th, w2Tl, DFF, Cc,
                                                       (size_t)Cc*DFF, (size_t)Cc*DFF);
    transpose_split_g<<<dim3(VPAD/32, Cc/32, 1), tb>>>(lmw, lmTh, lmTl, Cc, Vv, 0, 0);

    for (int l = 0; l < Ll; l++) {
        size_t oQ = (size_t)l * QKVN * Cc;
        size_t o2 = (size_t)l * Cc * Cc;
        size_t oF = (size_t)l * Cc * DFF;

        if (l > 0) {
            ln_split_kernel<<<BT, 256>>>(x, ln1g + l*Cc, ln1b + l*Cc, hh, hl);
            tc_gemm<false,false,false,false><<<gQ, 256, GSM_SIZE>>>(
                hh, hl, qkvTh + oQ, qkvTl + oQ, nullptr, nullptr, qkv,
                nullptr, nullptr, QKVN, Cc, 1, QKVN);
            attn_kernel<<<Bb * Hh, 256, ATTN_SMEM>>>(qkv, ah, al);
        }

        tc_gemm<true,false,true,false><<<gC, 256, GSM_SIZE>>>(
            ah, al, pTh + o2, pTl + o2, projb + l*Cc, x, x, nullptr, nullptr,
            Cc, Cc, 1, Cc);

        ln_split_kernel<<<BT, 256>>>(x, ln2g + l*Cc, ln2b + l*Cc, hh, hl);

        tc_gemm<true,true,false,true><<<gF, 256, GSM_SIZE>>>(
            hh, hl, w1Th + oF, w1Tl + oF, b1 + l*DFF, nullptr, nullptr, fh, fl,
            DFF, Cc, 1, DFF);

        tc_gemm<true,false,true,false><<<gC, 256, GSM_SIZE>>>(
            fh, fl, w2Th + oF, w2Tl + oF, b2 + l*Cc, x, x, nullptr, nullptr,
            Cc, DFF, 1, Cc);
    }

    ln_split_kernel<<<BT, 256>>>(x, lnfg, lnfb, hh, hl);

    tc_gemm<true,false,false,false><<<gV, 256, GSM_SIZE>>>(
        hh, hl, lmTh, lmTl, lmb, nullptr, out, nullptr, nullptr,
        Vv, Cc, 4, VPAD);
}

// round 15
// speedup vs baseline: 1.1346x; 1.0706x over previous
#include <cuda_runtime.h>
#include <cuda_bf16.h>
#include <math.h>
#include <cstdint>

// tcgen05 is only legal on arch-specific targets (sm_103a / sm_100a).
// The harness's nvcc also runs a generic compute_103 PTX pass; guard so that
// pass compiles empty bodies (the sm_103a cubin is what actually runs).
#if !defined(__CUDA_ARCH__) || defined(__CUDA_ARCH_FEAT_SM103_ALL) || \
    defined(__CUDA_ARCH_FEAT_SM100_ALL) || defined(__CUDA_ARCH_FEAT_SM101_ALL)
#define HAS_TCGEN05 1
#else
#define HAS_TCGEN05 0
#endif

// Problem dims
#define Bb   128
#define Tt   128
#define Cc   256
#define Hh   4
#define HS   64
#define Ll   6
#define DFF  1024
#define Vv   10000
#define BT   (Bb*Tt)   // 16384
#define VPAD 10240     // 80*128 (LM head padded to 4-tile groups)
#define QKVN 768

// ================= PTX helpers (sm_103a tcgen05) ===========================
__device__ __forceinline__ uint32_t smem_to_u32(const void* p) {
    uint32_t a;
    asm("{ .reg .u64 t; cvta.to.shared.u64 t, %1; cvt.u32.u64 %0, t; }"
        : "=r"(a) : "l"(p));
    return a;
}

#if HAS_TCGEN05
__device__ __forceinline__ uint32_t elect_one_pred() {
    uint32_t pred;
    asm volatile(
        "{\n\t.reg .pred p;\n\telect.sync _|p, 0xFFFFFFFF;\n\t"
        "selp.b32 %0, 1, 0, p;\n\t}"
        : "=r"(pred));
    return pred;
}
#define TCGEN05_ALLOC(smem_addr, nCols) \
    asm volatile("tcgen05.alloc.cta_group::1.sync.aligned.shared::cta.b32 [%0], %1;" \
        :: "r"((uint32_t)(smem_addr)), "r"((uint32_t)(nCols)) : "memory")
#define TCGEN05_DEALLOC(tmem_addr, nCols) \
    asm volatile("tcgen05.dealloc.cta_group::1.sync.aligned.b32 %0, %1;" \
        :: "r"(tmem_addr), "r"((uint32_t)(nCols)))
#define TCGEN05_RELINQ() \
    asm volatile("tcgen05.relinquish_alloc_permit.cta_group::1.sync.aligned;")
#define TCGEN05_COMMIT(mbar) \
    asm volatile("tcgen05.commit.cta_group::1.mbarrier::arrive::one.shared::cluster.b64 [%0];" \
        :: "r"((uint32_t)(mbar)) : "memory")
#define TCGEN05_FENCE_BEFORE() \
    asm volatile("tcgen05.fence::before_thread_sync;" ::: "memory")
#define TCGEN05_FENCE_AFTER() \
    asm volatile("tcgen05.fence::after_thread_sync;" ::: "memory")
#define TCGEN05_WAIT_LD() \
    asm volatile("tcgen05.wait::ld.sync.aligned;" ::: "memory")
#define FENCE_PROXY_ASYNC_SHARED_CTA() \
    asm volatile("fence.proxy.async.shared::cta;" ::: "memory")
#define MBARRIER_INIT(mbar, count) \
    asm volatile("mbarrier.init.shared.b64 [%0], %1;" \
        :: "r"((uint32_t)(mbar)), "r"((uint32_t)(count)) : "memory")
#define MBARRIER_INVAL(mbar) \
    asm volatile("mbarrier.inval.shared.b64 [%0];" :: "r"((uint32_t)(mbar)) : "memory")
// Non-blocking poll: mbarrier.test_wait in a spin loop, no sleep.
#define MBARRIER_POLL(mbar, parity) do { \
    uint32_t _mbar = (uint32_t)(mbar); \
    uint32_t _par  = (uint32_t)(parity); \
    uint32_t _done = 0; \
    while (!_done) { \
        asm volatile( \
            "{\n\t.reg .pred p;\n\t" \
            "mbarrier.test_wait.parity.acquire.cta.shared::cta.b64 p, [%1], %2;\n\t" \
            "selp.b32 %0, 1, 0, p;\n\t}" \
            : "=r"(_done) : "r"(_mbar), "r"(_par) : "memory"); \
    } \
} while (0)
// Async 16B copy global->shared (LDGSTS). Register-free, deep MLP.
__device__ __forceinline__ void cp_async16(uint32_t dst, const void* src) {
    asm volatile("cp.async.cg.shared.global [%0], [%1], 16;"
        :: "r"(dst), "l"(src) : "memory");
}
#define CP_ASYNC_COMMIT() asm volatile("cp.async.commit_group;" ::: "memory")
#define CP_ASYNC_WAIT0()  asm volatile("cp.async.wait_group 0;" ::: "memory")
#define TCGEN05_LD_32X32B_X32(r, tmem_addr) \
    asm volatile( \
        "tcgen05.ld.sync.aligned.32x32b.x32.b32 " \
        "{%0, %1, %2, %3, %4, %5, %6, %7, " \
        " %8, %9, %10, %11, %12, %13, %14, %15, " \
        " %16, %17, %18, %19, %20, %21, %22, %23, " \
        " %24, %25, %26, %27, %28, %29, %30, %31}, [%32];" \
        : "=r"((r)[0]),  "=r"((r)[1]),  "=r"((r)[2]),  "=r"((r)[3]), \
          "=r"((r)[4]),  "=r"((r)[5]),  "=r"((r)[6]),  "=r"((r)[7]), \
          "=r"((r)[8]),  "=r"((r)[9]),  "=r"((r)[10]), "=r"((r)[11]), \
          "=r"((r)[12]), "=r"((r)[13]), "=r"((r)[14]), "=r"((r)[15]), \
          "=r"((r)[16]), "=r"((r)[17]), "=r"((r)[18]), "=r"((r)[19]), \
          "=r"((r)[20]), "=r"((r)[21]), "=r"((r)[22]), "=r"((r)[23]), \
          "=r"((r)[24]), "=r"((r)[25]), "=r"((r)[26]), "=r"((r)[27]), \
          "=r"((r)[28]), "=r"((r)[29]), "=r"((r)[30]), "=r"((r)[31]) \
        : "r"(tmem_addr))

// cg1 bf16 SS MMA (A in SMEM, B in SMEM), fp32 accumulate
__device__ __forceinline__ void mma_bf16_ss(uint32_t d, uint64_t a, uint64_t b,
                                            uint32_t idesc, bool en) {
    uint32_t e = en ? 1u : 0u;
    asm volatile(
        "{\n\t.reg .pred p;\n\t"
        "setp.ne.u32 p, %5, 0;\n\t"
        "tcgen05.mma.cta_group::1.kind::f16 [%0], %1, %2, %3, {%4, %4, %4, %4}, p;\n\t}"
        :: "r"(d), "l"(a), "l"(b), "r"(idesc), "r"(0u), "r"(e)
        : "memory");
}
#endif  // HAS_TCGEN05

// 64-bit SMEM descriptor: SW128, Blackwell v1, LBO=1, SBO=64 (K-major 128B rows)
static __device__ __forceinline__ uint64_t make_desc_sw128(uint32_t addr) {
    const uint64_t base =
        (uint64_t(2)  << 61) | (uint64_t(1) << 46) |
        (uint64_t(64) << 32) | (uint64_t(1) << 16);
    return base | ((uint64_t)(addr >> 4) & 0x3FFF);
}
#define SW128(bo) ((bo) ^ (((bo) >> 3) & 0x70))

// ================= scratch (device globals) ================================
__device__ __align__(16) float g_x  [BT*Cc];
__device__ __align__(16) float g_qkv[BT*QKVN];
// bf16 hi/lo activations
__device__ __align__(16) __nv_bfloat16 g_hh[BT*Cc],  g_hl[BT*Cc];
__device__ __align__(16) __nv_bfloat16 g_ah[BT*Cc],  g_al[BT*Cc];
__device__ __align__(16) __nv_bfloat16 g_fh[BT*DFF], g_fl[BT*DFF];
// transposed+split weights: [N(pad), K] K-major
__device__ __align__(16) __nv_bfloat16 g_qkvT_h[Ll*QKVN*Cc], g_qkvT_l[Ll*QKVN*Cc];
__device__ __align__(16) __nv_bfloat16 g_pT_h [Ll*Cc*Cc],    g_pT_l [Ll*Cc*Cc];
__device__ __align__(16) __nv_bfloat16 g_w1T_h[Ll*DFF*Cc],   g_w1T_l[Ll*DFF*Cc];
__device__ __align__(16) __nv_bfloat16 g_w2T_h[Ll*Cc*DFF],   g_w2T_l[Ll*Cc*DFF];
__device__ __align__(16) __nv_bfloat16 g_lmT_h[VPAD*Cc],     g_lmT_l[VPAD*Cc];

// ================= small kernels ===========================================
// Fused embedding + LN1(layer 0): one block per row. Writes x AND hh/hl.
__global__ void embed_ln_kernel(const int* __restrict__ idx,
                                const float* __restrict__ tok,
                                const float* __restrict__ pos,
                                const float* __restrict__ g,
                                const float* __restrict__ b,
                                float* __restrict__ x,
                                __nv_bfloat16* __restrict__ oh,
                                __nv_bfloat16* __restrict__ ol) {
    int row = blockIdx.x;
    int tid = threadIdx.x;
    int t   = row & (Tt - 1);
    float v = tok[idx[row] * Cc + tid] + pos[t * Cc + tid];
    x[row * Cc + tid] = v;
    float s = v, s2 = v * v;
    #pragma unroll
    for (int off = 16; off > 0; off >>= 1) {
        s  += __shfl_xor_sync(0xffffffffu, s,  off);
        s2 += __shfl_xor_sync(0xffffffffu, s2, off);
    }
    __shared__ float ss[8], ss2[8];
    __shared__ float mean_s, rstd_s;
    int w = tid >> 5, l = tid & 31;
    if (l == 0) { ss[w] = s; ss2[w] = s2; }
    __syncthreads();
    if (tid == 0) {
        float S = 0.f, S2 = 0.f;
        #pragma unroll
        for (int i = 0; i < 8; i++) { S += ss[i]; S2 += ss2[i]; }
        float m   = S * (1.0f / Cc);
        float var = S2 * (1.0f / Cc) - m * m;
        mean_s = m;
        rstd_s = rsqrtf(var + 1e-5f);
    }
    __syncthreads();
    float y = (v - mean_s) * rstd_s * g[tid] + b[tid];
    __nv_bfloat16 hi = __float2bfloat16(y);
    oh[row * Cc + tid] = hi;
    ol[row * Cc + tid] = __float2bfloat16(y - __bfloat162float(hi));
}

// generic: W [K,N] fp32 (layer-strided) -> out [Npad,K] bf16 hi/lo
__global__ void transpose_split_g(const float* __restrict__ W,
                                  __nv_bfloat16* __restrict__ oh,
                                  __nv_bfloat16* __restrict__ ol,
                                  int K, int N,
                                  size_t wstride, size_t ostride) {
    __shared__ float t[32][33];
    int l  = blockIdx.z;
    W  += (size_t)l * wstride;
    oh += (size_t)l * ostride;
    ol += (size_t)l * ostride;
    int n0 = blockIdx.x * 32, k0 = blockIdx.y * 32;
    int tx = threadIdx.x, ty = threadIdx.y;
    #pragma unroll
    for (int i = 0; i < 4; i++) {
        int k = k0 + ty + i * 8;
        int n = n0 + tx;
        t[ty + i * 8][tx] = (n < N) ? W[(size_t)k * N + n] : 0.f;
    }
    __syncthreads();
    #pragma unroll
    for (int i = 0; i < 4; i++) {
        int n = n0 + ty + i * 8;
        int k = k0 + tx;
        float v = t[tx][ty + i * 8];
        __nv_bfloat16 hi = __float2bfloat16(v);
        oh[(size_t)n * K + k] = hi;
        ol[(size_t)n * K + k] = __float2bfloat16(v - __bfloat162float(hi));
    }
}

// fused QKV transpose: wq/wk/wv [L][256][256] -> out [L][768][256]
__global__ void qkv_transpose(const float* __restrict__ wq,
                              const float* __restrict__ wk,
                              const float* __restrict__ wv,
                              __nv_bfloat16* __restrict__ oh,
                              __nv_bfloat16* __restrict__ ol) {
    __shared__ float t[32][33];
    int l  = blockIdx.z;
    int n0 = blockIdx.x * 32, k0 = blockIdx.y * 32;
    const float* W;
    int nb;
    if      (n0 < 256) { W = wq + (size_t)l * Cc * Cc; nb = n0; }
    else if (n0 < 512) { W = wk + (size_t)l * Cc * Cc; nb = n0 - 256; }
    else               { W = wv + (size_t)l * Cc * Cc; nb = n0 - 512; }
    oh += (size_t)l * QKVN * Cc;
    ol += (size_t)l * QKVN * Cc;
    int tx = threadIdx.x, ty = threadIdx.y;
    #pragma unroll
    for (int i = 0; i < 4; i++) {
        int k = k0 + ty + i * 8;
        t[ty + i * 8][tx] = W[(size_t)k * Cc + nb + tx];
    }
    __syncthreads();
    #pragma unroll
    for (int i = 0; i < 4; i++) {
        int n = n0 + ty + i * 8;
        int k = k0 + tx;
        float v = t[tx][ty + i * 8];
        __nv_bfloat16 hi = __float2bfloat16(v);
        oh[(size_t)n * Cc + k] = hi;
        ol[(size_t)n * Cc + k] = __float2bfloat16(v - __bfloat162float(hi));
    }
}

// LayerNorm, warp-per-row (no smem, no block barrier). 8 rows per CTA.
__global__ void ln_split_kernel(const float* __restrict__ x,
                                const float* __restrict__ g,
                                const float* __restrict__ b,
                                __nv_bfloat16* __restrict__ oh,
                                __nv_bfloat16* __restrict__ ol) {
    const int lane = threadIdx.x & 31;
    const int row  = blockIdx.x * 8 + (threadIdx.x >> 5);
    const float* xr = x + (size_t)row * Cc;
    const int c0 = lane * 4;
    const int c1 = 128 + lane * 4;

    float4 v0 = *(const float4*)&xr[c0];
    float4 v1 = *(const float4*)&xr[c1];
    float s  = v0.x + v0.y + v0.z + v0.w + v1.x + v1.y + v1.z + v1.w;
    float s2 = v0.x*v0.x + v0.y*v0.y + v0.z*v0.z + v0.w*v0.w
             + v1.x*v1.x + v1.y*v1.y + v1.z*v1.z + v1.w*v1.w;
    #pragma unroll
    for (int off = 16; off > 0; off >>= 1) {
        s  += __shfl_xor_sync(0xffffffffu, s,  off);
        s2 += __shfl_xor_sync(0xffffffffu, s2, off);
    }
    float m    = s * (1.0f / Cc);
    float var  = s2 * (1.0f / Cc) - m * m;
    float rstd = rsqrtf(var + 1e-5f);

    float4 g0 = *(const float4*)&g[c0];
    float4 g1 = *(const float4*)&g[c1];
    float4 b0 = *(const float4*)&b[c0];
    float4 b1 = *(const float4*)&b[c1];

    float y[8];
    y[0] = (v0.x - m) * rstd * g0.x + b0.x;
    y[1] = (v0.y - m) * rstd * g0.y + b0.y;
    y[2] = (v0.z - m) * rstd * g0.z + b0.z;
    y[3] = (v0.w - m) * rstd * g0.w + b0.w;
    y[4] = (v1.x - m) * rstd * g1.x + b1.x;
    y[5] = (v1.y - m) * rstd * g1.y + b1.y;
    y[6] = (v1.z - m) * rstd * g1.z + b1.z;
    y[7] = (v1.w - m) * rstd * g1.w + b1.w;

    __nv_bfloat16* ohr = oh + (size_t)row * Cc;
    __nv_bfloat16* olr = ol + (size_t)row * Cc;
    #pragma unroll
    for (int half = 0; half < 2; half++) {
        int c = half ? c1 : c0;
        __nv_bfloat162 h01, h23, l01, l23;
        float* yy = y + half * 4;
        __nv_bfloat16 h0 = __float2bfloat16(yy[0]);
        __nv_bfloat16 h1b = __float2bfloat16(yy[1]);
        __nv_bfloat16 h2 = __float2bfloat16(yy[2]);
        __nv_bfloat16 h3 = __float2bfloat16(yy[3]);
        h01.x = h0; h01.y = h1b; h23.x = h2; h23.y = h3;
        l01.x = __float2bfloat16(yy[0] - __bfloat162float(h0));
        l01.y = __float2bfloat16(yy[1] - __bfloat162float(h1b));
        l23.x = __float2bfloat16(yy[2] - __bfloat162float(h2));
        l23.y = __float2bfloat16(yy[3] - __bfloat162float(h3));
        *(__nv_bfloat162*)&ohr[c]     = h01;
        *(__nv_bfloat162*)&ohr[c + 2] = h23;
        *(__nv_bfloat162*)&olr[c]     = l01;
        *(__nv_bfloat162*)&olr[c + 2] = l23;
    }
}

// ================= tcgen05 GEMM (cp.async loads, coalesced epilogue) ========
// Identical to R8-R14 (the winners) — protect the win.
#define GSM_TPTR 0
#define GSM_MBAR 8
#define GSM_AH   1024
#define GSM_AL   (1024 + 16384)
#define GSM_BH   (1024 + 32768)
#define GSM_BL   (1024 + 49152)
#define EPI_PAD  132                       // fp32 row pitch (16B-aligned rows)
#define GSM_SIZE (1024 + 128*EPI_PAD*4)    // 68608 >= 1024+65536 operand area
#define GEMM_IDESC 0x8200490u   // f32 acc, bf16 a/b, N=128, M=128

template<bool BIAS, bool RELU, bool RESID, bool SPLIT>
__global__ __launch_bounds__(256)
void tc_gemm(const __nv_bfloat16* __restrict__ Ah, const __nv_bfloat16* __restrict__ Al,
             const __nv_bfloat16* __restrict__ Bh, const __nv_bfloat16* __restrict__ Bl,
             const float* __restrict__ bias, const float* __restrict__ res,
             float* __restrict__ outf,
             __nv_bfloat16* __restrict__ oh, __nv_bfloat16* __restrict__ ol,
             int Nstore, int K, int ntiles, int Npad) {
#if HAS_TCGEN05
    extern __shared__ char smem[];
    const uint32_t smem_base = smem_to_u32(smem);
    const int tid  = threadIdx.x;
    const int wid  = tid >> 5;
    const int lane = tid & 31;
    const int bm   = blockIdx.y * 128;
    const int bn0  = blockIdx.x * 128 * ntiles;

    if (wid == 0) {
        TCGEN05_ALLOC(smem_base + GSM_TPTR, 128);
        TCGEN05_RELINQ();
    }
    if (tid == 0) MBARRIER_INIT(smem_base + GSM_MBAR, 1);
    __syncthreads();
    uint32_t tmem;
    asm volatile("ld.shared.b32 %0, [%1];" : "=r"(tmem) : "r"(smem_base + GSM_TPTR));

    const uint64_t dAh = make_desc_sw128(smem_base + GSM_AH);
    const uint64_t dAl = make_desc_sw128(smem_base + GSM_AL);
    const uint64_t dBh = make_desc_sw128(smem_base + GSM_BH);
    const uint64_t dBl = make_desc_sw128(smem_base + GSM_BL);

    // per-thread load mapping: 4 iters x one 16B vector per tile buffer
    const int lr = tid >> 3;            // row base 0..31 (+32*i)
    const int lb = (tid & 7) * 16;      // byte offset in 128B row

    const int nchunks = K >> 6;   // K/64
    int cc = 0;                   // global chunk counter (mbarrier parity)

    for (int t = 0; t < ntiles; t++) {
        const int bn = bn0 + t * 128;
        if (bn >= Npad) break;

        for (int c = 0; c < nchunks; c++) {
            const int k0 = c << 6;
            #pragma unroll
            for (int i = 0; i < 4; i++) {
                int r = lr + i * 32;
                uint32_t so = SW128(r * 128 + lb);
                const char* sa = (const char*)(Ah + (size_t)(bm + r) * K + k0) + lb;
                const char* sb = (const char*)(Al + (size_t)(bm + r) * K + k0) + lb;
                const char* sc = (const char*)(Bh + (size_t)(bn + r) * K + k0) + lb;
                const char* sd = (const char*)(Bl + (size_t)(bn + r) * K + k0) + lb;
                cp_async16(smem_base + GSM_AH + so, sa);
                cp_async16(smem_base + GSM_AL + so, sb);
                cp_async16(smem_base + GSM_BH + so, sc);
                cp_async16(smem_base + GSM_BL + so, sd);
            }
            CP_ASYNC_COMMIT();
            CP_ASYNC_WAIT0();
            FENCE_PROXY_ASYNC_SHARED_CTA();
            __syncthreads();

            if (wid == 0 && elect_one_pred()) {
                #pragma unroll
                for (int ks = 0; ks < 4; ks++) {
                    uint64_t oa = (uint64_t)(ks * 2);
                    mma_bf16_ss(tmem, dAh + oa, dBh + oa, GEMM_IDESC, !(c == 0 && ks == 0));
                    mma_bf16_ss(tmem, dAh + oa, dBl + oa, GEMM_IDESC, true);
                    mma_bf16_ss(tmem, dAl + oa, dBh + oa, GEMM_IDESC, true);
                }
                TCGEN05_COMMIT(smem_base + GSM_MBAR);
            }
            // warp 0 polls (no sleep), everyone else joins at the barrier
            if (wid == 0) MBARRIER_POLL(smem_base + GSM_MBAR, cc & 1);
            __syncthreads();
            cc++;
        }
        TCGEN05_FENCE_AFTER();

        // ---- epilogue: transpose through smem, fully coalesced stores ----
        {
            float* eps = (float*)(smem + GSM_AH);   // reuse operand smem
            const int wp   = wid & 3;
            const int colg = (wid >> 2) * 64;
            const int ml   = wp * 32 + lane;        // local row (m)
            #pragma unroll
            for (int half = 0; half < 2; half++) {
                int cb = colg + half * 32;
                uint32_t r[32];
                TCGEN05_LD_32X32B_X32(r, tmem + cb);
                TCGEN05_WAIT_LD();
                #pragma unroll
                for (int j = 0; j < 32; j++)
                    eps[ml * EPI_PAD + cb + j] = __uint_as_float(r[j]);
            }
            TCGEN05_FENCE_BEFORE();
            __syncthreads();

            // 128 rows x 32 float4-cols = 4096 quads; 256 threads x 16 iters.
            #pragma unroll 4
            for (int it = 0; it < 16; it++) {
                int q   = it * 256 + tid;
                int row = q >> 5;
                int c4  = (q & 31) << 2;
                int n   = bn + c4;
                if (n < Nstore) {
                    float4 v = *(const float4*)&eps[row * EPI_PAD + c4];
                    float vals[4] = {v.x, v.y, v.z, v.w};
                    size_t base = (size_t)(bm + row) * Nstore + n;
                    #pragma unroll
                    for (int e = 0; e < 4; e++) {
                        if (BIAS) vals[e] += bias[n + e];
                        if (RELU) vals[e] = fmaxf(vals[e], 0.f);
                    }
                    if (SPLIT) {
                        #pragma unroll
                        for (int e = 0; e < 4; e++) {
                            __nv_bfloat16 hi = __float2bfloat16(vals[e]);
                            oh[base + e] = hi;
                            ol[base + e] = __float2bfloat16(vals[e] - __bfloat162float(hi));
                        }
                    } else {
                        if (RESID) {
                            float4 rv = *(const float4*)&res[base];
                            vals[0] += rv.x; vals[1] += rv.y;
                            vals[2] += rv.z; vals[3] += rv.w;
                        }
                        float4 o;
                        o.x = vals[0]; o.y = vals[1]; o.z = vals[2]; o.w = vals[3];
                        *(float4*)&outf[base] = o;
                    }
                }
            }
            __syncthreads();   // eps dead before next tile's operand loads
        }
    }

    if (tid == 0) MBARRIER_INVAL(smem_base + GSM_MBAR);
    __syncthreads();
    if (wid == 0) TCGEN05_DEALLOC(tmem, 128);
#endif  // HAS_TCGEN05
}

// ================= fused causal attention (balanced 8-row passes) ===========
// smem: Kst[64][128] (32KB) + Vs[128][68] (34KB) + stg[8][1024] (32KB) = 98KB
// Pass 0: rows w*8..; pass 1: rows 64+(7-w)*8.. — reversing pass-1 balances
// per-warp causal work (PV iters 136 for every warp instead of 80..192).
#define ATTN_SMEM ((64*128 + 128*68 + 8*1024) * 4)   // 100352 B

template<int NG>
__device__ __forceinline__ void qk_groups(const float* __restrict__ Kst,
                                          const float* __restrict__ sw,
                                          int lane, float s[8][4]) {
    #pragma unroll 4
    for (int d = 0; d < 64; d++) {
        const float* kd = &Kst[d * 128];
        float k[NG];
        #pragma unroll
        for (int e = 0; e < NG; e++) k[e] = kd[lane + 32 * e];
        float4 qa = *(const float4*)&sw[d * 8];       // rows 0-3 (broadcast)
        float4 qb = *(const float4*)&sw[d * 8 + 4];   // rows 4-7 (broadcast)
        float qv[8] = {qa.x, qa.y, qa.z, qa.w, qb.x, qb.y, qb.z, qb.w};
        #pragma unroll
        for (int i = 0; i < 8; i++)
            #pragma unroll
            for (int e = 0; e < NG; e++)
                s[i][e] = fmaf(qv[i], k[e], s[i][e]);
    }
}

__global__ __launch_bounds__(256)
void attn_kernel(const float* __restrict__ qkv,
                 __nv_bfloat16* __restrict__ oh, __nv_bfloat16* __restrict__ ol) {
    extern __shared__ float sm[];
    float* Kst = sm;                                 // [64][128] d-major
    float* Vs  = sm + 64 * 128;                      // [128][68]
    float* stg = sm + 64 * 128 + 128 * 68;           // [8][1024] union q/p

    const int b    = blockIdx.x >> 2;
    const int h    = blockIdx.x & 3;
    const int tid  = threadIdx.x;                    // 0..255
    const int lane = tid & 31;
    const int w    = tid >> 5;                       // 0..7

    const float* base_bt = qkv + (size_t)(b * Tt) * QKVN + h * HS;

    // Load K (transposed) and V: thread pair (row = tid>>1) covers one row.
    {
        const int row   = tid >> 1;
        const int dhalf = (tid & 1) * 32;
        const float* krow = base_bt + 256 + (size_t)row * QKVN + dhalf;
        const float* vrow = base_bt + 512 + (size_t)row * QKVN + dhalf;
        #pragma unroll
        for (int d4 = 0; d4 < 8; d4++) {
            int d = dhalf + d4 * 4;
            float4 kv = *(const float4*)(krow + d4 * 4);
            Kst[(d + 0) * 128 + row] = kv.x;
            Kst[(d + 1) * 128 + row] = kv.y;
            Kst[(d + 2) * 128 + row] = kv.z;
            Kst[(d + 3) * 128 + row] = kv.w;
            *(float4*)&Vs[row * 68 + d] = *(const float4*)(vrow + d4 * 4);
        }
    }
    __syncthreads();

    const float scale = 0.0625f;  // 256^-0.5
    float* sw = stg + w * 1024;   // union: q [d][8] then p [kk][8]

    #pragma unroll
    for (int pass = 0; pass < 2; pass++) {
        // pass-1 row reversal balances causal work across warps
        const int r0   = (pass == 0) ? (w * 8) : (64 + (7 - w) * 8);
        const int kmax = r0 + 7;
        const int ng   = (kmax >> 5) + 1;     // live key groups (warp-uniform)

        // stage q: lane j covers d = j and d = j+32 for all 8 rows
        #pragma unroll
        for (int half = 0; half < 2; half++) {
            int d = lane + half * 32;
            const float* qc = base_bt + (size_t)r0 * QKVN + d;
            float q0 = qc[0*QKVN], q1 = qc[1*QKVN], q2 = qc[2*QKVN], q3 = qc[3*QKVN];
            float q4 = qc[4*QKVN], q5 = qc[5*QKVN], q6 = qc[6*QKVN], q7 = qc[7*QKVN];
            float4 a; a.x = q0; a.y = q1; a.z = q2; a.w = q3;
            float4 c; c.x = q4; c.y = q5; c.z = q6; c.w = q7;
            *(float4*)&sw[d * 8]     = a;
            *(float4*)&sw[d * 8 + 4] = c;
        }
        __syncwarp();

        // scores: s[i][e] for key kk = lane + 32*e (only e < ng computed)
        float s[8][4];
        #pragma unroll
        for (int i = 0; i < 8; i++)
            #pragma unroll
            for (int e = 0; e < 4; e++) s[i][e] = 0.f;

        if      (ng == 1) qk_groups<1>(Kst, sw, lane, s);
        else if (ng == 2) qk_groups<2>(Kst, sw, lane, s);
        else if (ng == 3) qk_groups<3>(Kst, sw, lane, s);
        else              qk_groups<4>(Kst, sw, lane, s);
        __syncwarp();   // q reads done before p overwrites sw

        // softmax per row (e >= ng stays masked: kk = lane+32e > kmax >= qr)
        #pragma unroll
        for (int i = 0; i < 8; i++) {
            const int qr = r0 + i;
            float e[4];
            float mx = -1e30f;
            #pragma unroll
            for (int ee = 0; ee < 4; ee++) {
                int kk = lane + 32 * ee;
                float sv = s[i][ee] * scale;
                s[i][ee] = sv;
                if (kk <= qr) mx = fmaxf(mx, sv);
            }
            #pragma unroll
            for (int off = 16; off > 0; off >>= 1)
                mx = fmaxf(mx, __shfl_xor_sync(0xffffffffu, mx, off));
            float sum = 0.f;
            #pragma unroll
            for (int ee = 0; ee < 4; ee++) {
                int kk = lane + 32 * ee;
                e[ee] = (kk <= qr) ? __expf(s[i][ee] - mx) : 0.f;
                sum += e[ee];
            }
            #pragma unroll
            for (int off = 16; off > 0; off >>= 1)
                sum += __shfl_xor_sync(0xffffffffu, sum, off);
            float rs = 1.0f / sum;
            #pragma unroll
            for (int ee = 0; ee < 4; ee++) s[i][ee] = e[ee] * rs;  // reuse s as p
        }
        // stage p only for live groups (PV never reads kk > kmax)
        for (int ee = 0; ee < ng; ee++) {
            int kk = lane + 32 * ee;
            float4 pa; pa.x = s[0][ee]; pa.y = s[1][ee]; pa.z = s[2][ee]; pa.w = s[3][ee];
            float4 pb; pb.x = s[4][ee]; pb.y = s[5][ee]; pb.z = s[6][ee]; pb.w = s[7][ee];
            *(float4*)&sw[kk * 8]     = pa;
            *(float4*)&sw[kk * 8 + 4] = pb;
        }
        __syncwarp();

        // PV: lane owns dims d0 = 2*lane, d1 = 2*lane+1
        float o[8][2];
        #pragma unroll
        for (int i = 0; i < 8; i++) { o[i][0] = 0.f; o[i][1] = 0.f; }
        #pragma unroll 2
        for (int kk = 0; kk <= kmax; kk++) {
            float2 v = *(const float2*)&Vs[kk * 68 + 2 * lane];
            float4 pa = *(const float4*)&sw[kk * 8];       // rows 0-3 (broadcast)
            float4 pb = *(const float4*)&sw[kk * 8 + 4];   // rows 4-7 (broadcast)
            o[0][0] = fmaf(pa.x, v.x, o[0][0]); o[0][1] = fmaf(pa.x, v.y, o[0][1]);
            o[1][0] = fmaf(pa.y, v.x, o[1][0]); o[1][1] = fmaf(pa.y, v.y, o[1][1]);
            o[2][0] = fmaf(pa.z, v.x, o[2][0]); o[2][1] = fmaf(pa.z, v.y, o[2][1]);
            o[3][0] = fmaf(pa.w, v.x, o[3][0]); o[3][1] = fmaf(pa.w, v.y, o[3][1]);
            o[4][0] = fmaf(pb.x, v.x, o[4][0]); o[4][1] = fmaf(pb.x, v.y, o[4][1]);
            o[5][0] = fmaf(pb.y, v.x, o[5][0]); o[5][1] = fmaf(pb.y, v.y, o[5][1]);
            o[6][0] = fmaf(pb.z, v.x, o[6][0]); o[6][1] = fmaf(pb.z, v.y, o[6][1]);
            o[7][0] = fmaf(pb.w, v.x, o[7][0]); o[7][1] = fmaf(pb.w, v.y, o[7][1]);
        }

        #pragma unroll
        for (int i = 0; i < 8; i++) {
            size_t obase = (size_t)(b * Tt + r0 + i) * Cc + h * HS + 2 * lane;
            __nv_bfloat16 h0 = __float2bfloat16(o[i][0]);
            __nv_bfloat16 h1 = __float2bfloat16(o[i][1]);
            oh[obase]     = h0;
            oh[obase + 1] = h1;
            ol[obase]     = __float2bfloat16(o[i][0] - __bfloat162float(h0));
            ol[obase + 1] = __float2bfloat16(o[i][1] - __bfloat162float(h1));
        }
        __syncwarp();   // sw reused next pass
    }
}

// ================= launch ===================================================
extern "C" void kernel_launch(void* const* d_in, const int* in_sizes, int n_in,
                              void* d_out, int out_size) {
    const int*   idx   = (const int*)  d_in[0];
    const float* tok   = (const float*)d_in[1];
    const float* pos   = (const float*)d_in[2];
    const float* ln1g  = (const float*)d_in[3];
    const float* ln1b  = (const float*)d_in[4];
    const float* wq    = (const float*)d_in[5];
    const float* wk    = (const float*)d_in[6];
    const float* wv    = (const float*)d_in[7];
    const float* projw = (const float*)d_in[8];
    const float* projb = (const float*)d_in[9];
    const float* ln2g  = (const float*)d_in[10];
    const float* ln2b  = (const float*)d_in[11];
    const float* w1    = (const float*)d_in[12];
    const float* b1    = (const float*)d_in[13];
    const float* w2    = (const float*)d_in[14];
    const float* b2    = (const float*)d_in[15];
    const float* lnfg  = (const float*)d_in[16];
    const float* lnfb  = (const float*)d_in[17];
    const float* lmw   = (const float*)d_in[18];
    const float* lmb   = (const float*)d_in[19];
    float* out = (float*)d_out;

    float *x, *qkv;
    __nv_bfloat16 *hh, *hl, *ah, *al, *fh, *fl;
    __nv_bfloat16 *qkvTh, *qkvTl, *pTh, *pTl;
    __nv_bfloat16 *w1Th, *w1Tl, *w2Th, *w2Tl, *lmTh, *lmTl;
    cudaGetSymbolAddress((void**)&x,   g_x);
    cudaGetSymbolAddress((void**)&qkv, g_qkv);
    cudaGetSymbolAddress((void**)&hh, g_hh);  cudaGetSymbolAddress((void**)&hl, g_hl);
    cudaGetSymbolAddress((void**)&ah, g_ah);  cudaGetSymbolAddress((void**)&al, g_al);
    cudaGetSymbolAddress((void**)&fh, g_fh);  cudaGetSymbolAddress((void**)&fl, g_fl);
    cudaGetSymbolAddress((void**)&qkvTh, g_qkvT_h); cudaGetSymbolAddress((void**)&qkvTl, g_qkvT_l);
    cudaGetSymbolAddress((void**)&pTh,  g_pT_h);    cudaGetSymbolAddress((void**)&pTl,  g_pT_l);
    cudaGetSymbolAddress((void**)&w1Th, g_w1T_h);   cudaGetSymbolAddress((void**)&w1Tl, g_w1T_l);
    cudaGetSymbolAddress((void**)&w2Th, g_w2T_h);   cudaGetSymbolAddress((void**)&w2Tl, g_w2T_l);
    cudaGetSymbolAddress((void**)&lmTh, g_lmT_h);   cudaGetSymbolAddress((void**)&lmTl, g_lmT_l);

    cudaFuncSetAttribute(attn_kernel,
                         cudaFuncAttributeMaxDynamicSharedMemorySize, ATTN_SMEM);
    cudaFuncSetAttribute(tc_gemm<false,false,false,false>,
                         cudaFuncAttributeMaxDynamicSharedMemorySize, GSM_SIZE);
    cudaFuncSetAttribute(tc_gemm<true,false,true,false>,
                         cudaFuncAttributeMaxDynamicSharedMemorySize, GSM_SIZE);
    cudaFuncSetAttribute(tc_gemm<true,true,false,true>,
                         cudaFuncAttributeMaxDynamicSharedMemorySize, GSM_SIZE);
    cudaFuncSetAttribute(tc_gemm<true,false,false,false>,
                         cudaFuncAttributeMaxDynamicSharedMemorySize, GSM_SIZE);

    dim3 tb(32, 8);
    const dim3 gC(Cc / 128,   BT / 128);   // N=256
    const dim3 gQ(QKVN / 128, BT / 128);   // N=768
    const dim3 gF(DFF / 128,  BT / 128);   // N=1024
    const dim3 gV(VPAD / 512, BT / 128);   // LM head: 20 x 128, 4 N-tiles/CTA

    // Launch order: index 3 is the profiled launch -> attn_kernel.
    qkv_transpose<<<dim3(QKVN/32, Cc/32, Ll), tb>>>(wq, wk, wv, qkvTh, qkvTl);      // 0
    embed_ln_kernel<<<BT, 256>>>(idx, tok, pos, ln1g, ln1b, x, hh, hl);             // 1
    tc_gemm<false,false,false,false><<<gQ, 256, GSM_SIZE>>>(                        // 2
        hh, hl, qkvTh, qkvTl, nullptr, nullptr, qkv, nullptr, nullptr,
        QKVN, Cc, 1, QKVN);
    attn_kernel<<<Bb * Hh, 256, ATTN_SMEM>>>(qkv, ah, al);                          // 3 (PROFILED)
    transpose_split_g<<<dim3(Cc/32, Cc/32, Ll), tb>>>(projw, pTh, pTl, Cc, Cc,
                                                      (size_t)Cc*Cc, (size_t)Cc*Cc);
    transpose_split_g<<<dim3(DFF/32, Cc/32, Ll), tb>>>(w1, w1Th, w1Tl, Cc, DFF,
                                                       (size_t)Cc*DFF, (size_t)Cc*DFF);
    transpose_split_g<<<dim3(Cc/32, DFF/32, Ll), tb>>>(w2, w2Th, w2Tl, DFF, Cc,
                                                       (size_t)Cc*DFF, (size_t)Cc*DFF);
    transpose_split_g<<<dim3(VPAD/32, Cc/32, 1), tb>>>(lmw, lmTh, lmTl, Cc, Vv, 0, 0);

    for (int l = 0; l < Ll; l++) {
        size_t oQ = (size_t)l * QKVN * Cc;
        size_t o2 = (size_t)l * Cc * Cc;
        size_t oF = (size_t)l * Cc * DFF;

        if (l > 0) {
            ln_split_kernel<<<BT / 8, 256>>>(x, ln1g + l*Cc, ln1b + l*Cc, hh, hl);
            tc_gemm<false,false,false,false><<<gQ, 256, GSM_SIZE>>>(
                hh, hl, qkvTh + oQ, qkvTl + oQ, nullptr, nullptr, qkv,
                nullptr, nullptr, QKVN, Cc, 1, QKVN);
            attn_kernel<<<Bb * Hh, 256, ATTN_SMEM>>>(qkv, ah, al);
        }

        tc_gemm<true,false,true,false><<<gC, 256, GSM_SIZE>>>(
            ah, al, pTh + o2, pTl + o2, projb + l*Cc, x, x, nullptr, nullptr,
            Cc, Cc, 1, Cc);

        ln_split_kernel<<<BT / 8, 256>>>(x, ln2g + l*Cc, ln2b + l*Cc, hh, hl);

        tc_gemm<true,true,false,true><<<gF, 256, GSM_SIZE>>>(
            hh, hl, w1Th + oF, w1Tl + oF, b1 + l*DFF, nullptr, nullptr, fh, fl,
            DFF, Cc, 1, DFF);

        tc_gemm<true,false,true,false><<<gC, 256, GSM_SIZE>>>(
            fh, fl, w2Th + oF, w2Tl + oF, b2 + l*Cc, x, x, nullptr, nullptr,
            Cc, DFF, 1, Cc);
    }

    ln_split_kernel<<<BT / 8, 256>>>(x, lnfg, lnfb, hh, hl);

    tc_gemm<true,false,false,false><<<gV, 256, GSM_SIZE>>>(
        hh, hl, lmTh, lmTl, lmb, nullptr, out, nullptr, nullptr,
        Vv, Cc, 4, VPAD);
}